// round 12
// baseline (speedup 1.0000x reference)
#include <cuda_runtime.h>
#include <cuda_fp16.h>
#include <math.h>
#include <stdint.h>

#define BB 4
#define CC 64
#define MM 8
#define HH 224
#define WW 224
#define NN (HH*WW)      // 50176
#define BN (BB*NN)      // 200704
#define TPX 128         // pixels per CTA tile

// Scratch (static device globals — allocation-free per harness rules)
__device__ __half g_h[BB*CC*NN];
__device__ __half g_s[BB*CC*NN];
__device__ float g_Q[BB*MM*NN];
__device__ __half g_K[BB*MM*NN];
__device__ float g_KV[BB*MM*CC];
__device__ float g_Ksum[BB*MM];

__device__ __forceinline__ float relu6f(float x){ return fminf(fmaxf(x,0.f),6.f); }
__device__ __forceinline__ float softplusf(float x){
    return fmaxf(x,0.f) + __logf(1.f + __expf(-fabsf(x)));
}
__device__ __forceinline__ uint32_t smem_u32(const void* p){
    uint32_t a;
    asm("{ .reg .u64 t; cvta.to.shared.u64 t, %1; cvt.u32.u64 %0, t; }" : "=r"(a) : "l"(p));
    return a;
}
__device__ __forceinline__ uint32_t packh2(float a, float b){
    half2 h = __floats2half2_rn(a, b);
    return *(uint32_t*)&h;
}
__device__ __forceinline__ void ldsm4(uint32_t* r, uint32_t a){
    asm volatile("ldmatrix.sync.aligned.m8n8.x4.shared.b16 {%0,%1,%2,%3}, [%4];"
        : "=r"(r[0]),"=r"(r[1]),"=r"(r[2]),"=r"(r[3]) : "r"(a));
}
__device__ __forceinline__ void ldsm4t(uint32_t* r, uint32_t a){
    asm volatile("ldmatrix.sync.aligned.m8n8.x4.trans.shared.b16 {%0,%1,%2,%3}, [%4];"
        : "=r"(r[0]),"=r"(r[1]),"=r"(r[2]),"=r"(r[3]) : "r"(a));
}
__device__ __forceinline__ void mma16816h(float* d, const uint32_t* a, const uint32_t* b){
    asm volatile("mma.sync.aligned.m16n8k16.row.col.f32.f16.f16.f32 "
        "{%0,%1,%2,%3}, {%4,%5,%6,%7}, {%8,%9}, {%0,%1,%2,%3};"
        : "+f"(d[0]),"+f"(d[1]),"+f"(d[2]),"+f"(d[3])
        : "r"(a[0]),"r"(a[1]),"r"(a[2]),"r"(a[3]), "r"(b[0]),"r"(b[1]));
}

__global__ void k_zero(){
    int i = blockIdx.x*blockDim.x + threadIdx.x;
    if (i < BB*MM*CC) g_KV[i]   = 0.f;
    if (i < BB*MM)    g_Ksum[i] = 0.f;
}

// ---------------------------------------------------------------------------
// K1 front (fp16 mma.sync): D[144 out, 128 px] = W[144,64] x Xt[64,128]
// outputs: [v(0..63) | fc1(64..127) | q(128..135) | k(136..143)]
// 288 threads = 9 warps. KV-partial via 2nd MMA on V fragments (K staged f16).
// ---------------------------------------------------------------------------
#define F_WH  0
#define F_XH  20736
#define F_KS  20736     // alias of XH after mainloop: [16][136] f16 (rows 8-15 zero)
#define F_CST 38144
#define F_SMEM 38976
#define WS 72     // weight smem row stride (f16 elems)
#define XS 136    // x smem row stride (f16 elems)
#define KS 136    // K_s row stride (f16 elems)

__global__ __launch_bounds__(288,2) void k_front(
    const float* __restrict__ x,
    const float* __restrict__ q_w, const float* __restrict__ q_b,
    const float* __restrict__ k_w, const float* __restrict__ k_b,
    const float* __restrict__ v_w, const float* __restrict__ v_b,
    const float* __restrict__ fc1_w, const float* __restrict__ fc1_bn)
{
    extern __shared__ char sm[];
    __half* wH = (__half*)(sm + F_WH);
    __half* xH = (__half*)(sm + F_XH);
    __half* K_s = (__half*)(sm + F_KS);
    float* s_vb   = (float*)(sm + F_CST);         // 64
    float* s_finv = s_vb + 64;                    // 64
    float* s_fbeta= s_finv + 64;                  // 64
    float* s_qb   = s_fbeta + 64;                 // 8
    float* s_kb   = s_qb + 8;                     // 8
    uint32_t sb = smem_u32(sm);

    int tid = threadIdx.x;
    int b  = blockIdx.y;
    int n0 = blockIdx.x * TPX;

    // weights: 144 x 64 -> fp16
    for (int i=tid; i<144*32; i+=288){
        int o = i>>5, c2 = (i&31)<<1;
        const float* src = (o<64) ? v_w + o*64
                         : (o<128)? fc1_w + (o-64)*64
                         : (o<136)? q_w + (o-128)*64
                         :          k_w + (o-136)*64;
        *(half2*)(wH + o*WS + c2) = __floats2half2_rn(src[c2], src[c2+1]);
    }
    // x tile: [64 ch][128 px] -> fp16
    const float* xb = x + (size_t)b*CC*NN + n0;
    for (int i=tid; i<64*64; i+=288){
        int c = i>>6, p2 = (i&63)<<1;
        float2 v = *(const float2*)(xb + (size_t)c*NN + p2);
        *(half2*)(xH + c*XS + p2) = __floats2half2_rn(v.x, v.y);
    }
    if (tid < 64){
        s_vb[tid] = v_b[tid];
        float sc=fc1_bn[0*CC+tid], bi=fc1_bn[1*CC+tid];
        float mn=fc1_bn[2*CC+tid], vr=fc1_bn[3*CC+tid];
        float inv = sc*rsqrtf(vr+1e-5f);
        s_finv[tid]=inv; s_fbeta[tid]=bi-mn*inv;
    } else if (tid < 72){
        s_qb[tid-64] = q_b[tid-64];
        s_kb[tid-64] = k_b[tid-64];
    }
    __syncthreads();

    int w = tid >> 5, lane = tid & 31;
    int m0 = w*16;

    float acc[16][4];
    #pragma unroll
    for (int i=0;i<16;i++){ acc[i][0]=acc[i][1]=acc[i][2]=acc[i][3]=0.f; }

    int arow = m0 + (lane & 15), acol8 = (lane>>4)*8;
    int brow = (lane & 7) + 8*((lane>>3)&1), bcol8 = (lane>>4)*8;

    #pragma unroll
    for (int kt=0; kt<4; kt++){
        int k0 = kt*16;
        uint32_t a[4];
        ldsm4(a, sb + F_WH + (uint32_t)(arow*WS + k0 + acol8)*2);
        #pragma unroll
        for (int np=0; np<8; np++){
            uint32_t bF[4];
            ldsm4t(bF, sb + F_XH + (uint32_t)((k0+brow)*XS + np*16 + bcol8)*2);
            mma16816h(acc[2*np],   a, bF);
            mma16816h(acc[2*np+1], a, bF+2);
        }
    }

    __syncthreads();   // sync1: mainloop smem reads done -> K_s alias safe

    int g = lane >> 2, t2 = (lane & 3)*2;
    if (w < 4){
        // zero pad K_s rows 8..15 (2 rows per warp)
        int r0 = 8 + 2*w;
        for (int j=lane; j<KS; j+=32){
            K_s[r0*KS + j]     = __float2half(0.f);
            K_s[(r0+1)*KS + j] = __float2half(0.f);
        }
    } else if (w < 8){
        int o0 = m0 - 64 + g, o1 = o0 + 8;
        float i0=s_finv[o0], e0=s_fbeta[o0], i1=s_finv[o1], e1=s_fbeta[o1];
        __half* p0 = g_h + ((size_t)b*CC + o0)*NN + n0 + t2;
        __half* p1 = g_h + ((size_t)b*CC + o1)*NN + n0 + t2;
        #pragma unroll
        for (int nt=0; nt<16; nt++){
            *(half2*)(p0 + nt*8) = __floats2half2_rn(relu6f(acc[nt][0]*i0+e0), relu6f(acc[nt][1]*i0+e0));
            *(half2*)(p1 + nt*8) = __floats2half2_rn(relu6f(acc[nt][2]*i1+e1), relu6f(acc[nt][3]*i1+e1));
        }
    } else {
        // rows g -> Q[m=g], rows g+8 -> K[m=g]
        float bq = s_qb[g], bk = s_kb[g];
        float*  pq = g_Q + ((size_t)b*MM + g)*NN + n0 + t2;
        __half* pk = g_K + ((size_t)b*MM + g)*NN + n0 + t2;
        float ksum = 0.f;
        #pragma unroll
        for (int nt=0; nt<16; nt++){
            int px = nt*8 + t2;
            float q0 = softplusf(acc[nt][0]+bq), q1 = softplusf(acc[nt][1]+bq);
            float k0v = softplusf(acc[nt][2]+bk), k1v = softplusf(acc[nt][3]+bk);
            *(float2*)(pq + nt*8) = make_float2(q0, q1);
            half2 kk = __floats2half2_rn(k0v, k1v);
            *(half2*)(pk + nt*8) = kk;
            *(half2*)(K_s + g*KS + px) = kk;
            ksum += k0v + k1v;
        }
        ksum += __shfl_xor_sync(0xffffffffu, ksum, 1);
        ksum += __shfl_xor_sync(0xffffffffu, ksum, 2);
        if ((lane & 3) == 0) atomicAdd(&g_Ksum[b*MM + g], ksum);
    }
    __syncthreads();   // sync2: K_s ready

    // GEMM2: KV[m, ch] += sum_px K[m,px] * (Vconv[ch,px]+vb[ch])  (warps 0..3)
    if (w < 4){
        float vb0 = s_vb[m0+g], vb1 = s_vb[m0+8+g];
        float d2lo[4] = {0.f,0.f,0.f,0.f}, d2hi[4] = {0.f,0.f,0.f,0.f};
        #pragma unroll
        for (int np=0; np<8; np++){
            uint32_t aK[4];
            ldsm4(aK, sb + F_KS + (uint32_t)((lane&15)*KS + np*16 + (lane>>4)*8)*2);
            uint32_t bl[2], bh[2];
            bl[0] = packh2(acc[2*np][0]+vb0,   acc[2*np][1]+vb0);
            bl[1] = packh2(acc[2*np+1][0]+vb0, acc[2*np+1][1]+vb0);
            bh[0] = packh2(acc[2*np][2]+vb1,   acc[2*np][3]+vb1);
            bh[1] = packh2(acc[2*np+1][2]+vb1, acc[2*np+1][3]+vb1);
            mma16816h(d2lo, aK, bl);
            mma16816h(d2hi, aK, bh);
        }
        float* kvb = g_KV + b*MM*CC + g*CC;
        atomicAdd(kvb + m0 + t2,       d2lo[0]);
        atomicAdd(kvb + m0 + t2 + 1,   d2lo[1]);
        atomicAdd(kvb + m0+8 + t2,     d2hi[0]);
        atomicAdd(kvb + m0+8 + t2 + 1, d2hi[1]);
    }
}

// ---------------------------------------------------------------------------
// K2: depthwise 5x5 + 3x3 (both BN+ReLU6), summed -> g_s (fp16 in/out)
// ---------------------------------------------------------------------------
__global__ __launch_bounds__(256) void k_dw(
    const float* __restrict__ w5, const float* __restrict__ bn5,
    const float* __restrict__ w3, const float* __restrict__ bn3)
{
    int bc = blockIdx.z;
    int c  = bc & (CC-1);
    int y0 = blockIdx.y*16, x0 = blockIdx.x*32;

    __shared__ float t[20][36];
    __shared__ float s_w5[25], s_w3[9], s_c[4];

    int tid = threadIdx.y*16 + threadIdx.x;
    const __half* plane = g_h + (size_t)bc*NN;

    for (int i=tid;i<20*36;i+=256){
        int ly=i/36, lx=i%36;
        int gy=y0+ly-2, gx=x0+lx-2;
        float v = 0.f;
        if (gy>=0 && gy<HH && gx>=0 && gx<WW) v = __half2float(plane[gy*WW+gx]);
        t[ly][lx] = v;
    }
    if (tid<25) s_w5[tid] = w5[c*25+tid];
    if (tid<9)  s_w3[tid] = w3[c*9+tid];
    if (tid==0){
        float inv = bn5[0*CC+c]*rsqrtf(bn5[3*CC+c]+1e-5f);
        s_c[0]=inv; s_c[1]=bn5[1*CC+c]-bn5[2*CC+c]*inv;
    }
    if (tid==32){
        float inv = bn3[0*CC+c]*rsqrtf(bn3[3*CC+c]+1e-5f);
        s_c[2]=inv; s_c[3]=bn3[1*CC+c]-bn3[2*CC+c]*inv;
    }
    __syncthreads();

    int ty = threadIdx.y;        // 0..15 (row)
    int tx2 = threadIdx.x*2;     // 0,2,..,30 (2 px per thread)

    float a5a=0.f, a5b=0.f;
    #pragma unroll
    for (int i=0;i<5;i++){
        const float* r = &t[ty+i][tx2];
        float c0=r[0], c1=r[1], c2=r[2], c3=r[3], c4=r[4], c5=r[5];
        float w0=s_w5[i*5], w1=s_w5[i*5+1], w2=s_w5[i*5+2], w3v=s_w5[i*5+3], w4=s_w5[i*5+4];
        a5a = fmaf(w0,c0, fmaf(w1,c1, fmaf(w2,c2, fmaf(w3v,c3, fmaf(w4,c4, a5a)))));
        a5b = fmaf(w0,c1, fmaf(w1,c2, fmaf(w2,c3, fmaf(w3v,c4, fmaf(w4,c5, a5b)))));
    }
    float a3a=0.f, a3b=0.f;
    #pragma unroll
    for (int i=0;i<3;i++){
        const float* r = &t[ty+1+i][tx2+1];
        float c0=r[0], c1=r[1], c2=r[2], c3=r[3];
        float w0=s_w3[i*3], w1=s_w3[i*3+1], w2=s_w3[i*3+2];
        a3a = fmaf(w0,c0, fmaf(w1,c1, fmaf(w2,c2, a3a)));
        a3b = fmaf(w0,c1, fmaf(w1,c2, fmaf(w2,c3, a3b)));
    }

    float ra = relu6f(a5a*s_c[0]+s_c[1]) + relu6f(a3a*s_c[2]+s_c[3]);
    float rb = relu6f(a5b*s_c[0]+s_c[1]) + relu6f(a3b*s_c[2]+s_c[3]);
    *(half2*)(g_s + (size_t)bc*NN + (y0+ty)*WW + (x0+tx2)) = __floats2half2_rn(ra, rb);
}

// ---------------------------------------------------------------------------
// K3: fc2 (fp16 mma.sync) + KV via 2nd MMA on xc fragments.
// smem: AH 0 (9216), XH 9216 (17408), KS 26624 (4352), INV 30976, BETA 31232
// ---------------------------------------------------------------------------
#define C_AH  0
#define C_XH  9216
#define C_KS  26624
#define C_INV 30976
#define C_BETA 31232
#define C_SMEM 31488

__global__ __launch_bounds__(256,4) void k_fc2kv(
    const float* __restrict__ fc2_w, const float* __restrict__ fc2_bn)
{
    extern __shared__ char sm[];
    __half* aH = (__half*)(sm + C_AH);
    __half* xH = (__half*)(sm + C_XH);
    __half* K_s = (__half*)(sm + C_KS);
    float* s_inv = (float*)(sm + C_INV);
    float* s_beta= (float*)(sm + C_BETA);
    uint32_t sb = smem_u32(sm);

    int tid = threadIdx.x;
    int b  = blockIdx.y;
    int n0 = blockIdx.x * TPX;

    // weights 64x64 -> fp16
    for (int i=tid; i<64*32; i+=256){
        int o = i>>5, c2 = (i&31)<<1;
        *(half2*)(aH + o*WS + c2) = __floats2half2_rn(fc2_w[o*64+c2], fc2_w[o*64+c2+1]);
    }
    // s tile [64 ch][128 px] — raw fp16 copy
    const __half* sp = g_s + (size_t)b*CC*NN + n0;
    for (int i=tid; i<64*16; i+=256){
        int c = i>>4, p8 = (i&15)<<3;
        *(uint4*)(xH + c*XS + p8) = *(const uint4*)(sp + (size_t)c*NN + p8);
    }
    // K_s: rows 0..7 from g_K (fp16 raw), rows 8..15 zero
    {
        const __half* kp = g_K + (size_t)b*MM*NN + n0;
        for (int i=tid; i<8*16; i+=256){
            int m = i>>4, p8 = (i&15)<<3;
            *(uint4*)(K_s + m*KS + p8) = *(const uint4*)(kp + (size_t)m*NN + p8);
        }
        for (int i=tid; i<8*68; i+=256){
            int r = 8 + i/68, j = (i%68)*2;
            *(uint32_t*)(K_s + r*KS + j) = 0u;
        }
    }
    if (tid < 64){
        float sc=fc2_bn[0*CC+tid], bi=fc2_bn[1*CC+tid];
        float mn=fc2_bn[2*CC+tid], vr=fc2_bn[3*CC+tid];
        float inv = sc*rsqrtf(vr+1e-5f);
        s_inv[tid]=inv; s_beta[tid]=bi-mn*inv;
    }
    __syncthreads();

    int w = tid >> 5, lane = tid & 31;
    int mt = w & 3, ph = w >> 2;
    int m0 = mt*16, p0 = ph*64;

    float acc[8][4];
    #pragma unroll
    for (int i=0;i<8;i++){ acc[i][0]=acc[i][1]=acc[i][2]=acc[i][3]=0.f; }

    int arow = m0 + (lane & 15), acol8 = (lane>>4)*8;
    int brow = (lane & 7) + 8*((lane>>3)&1), bcol8 = (lane>>4)*8;

    #pragma unroll
    for (int kt=0; kt<4; kt++){
        int k0 = kt*16;
        uint32_t a[4];
        ldsm4(a, sb + C_AH + (uint32_t)(arow*WS + k0 + acol8)*2);
        #pragma unroll
        for (int np=0; np<4; np++){
            uint32_t bF[4];
            ldsm4t(bF, sb + C_XH + (uint32_t)((k0+brow)*XS + p0 + np*16 + bcol8)*2);
            mma16816h(acc[2*np],   a, bF);
            mma16816h(acc[2*np+1], a, bF+2);
        }
    }

    // GEMM2: KV[m, ch] += sum_px K[m,px] * relu6(bn(D[ch,px]))
    int g = lane >> 2, t2 = (lane & 3)*2;
    int o0 = m0 + g, o1 = o0 + 8;
    float i0 = s_inv[o0], e0 = s_beta[o0], i1 = s_inv[o1], e1 = s_beta[o1];
    float d2lo[4] = {0.f,0.f,0.f,0.f}, d2hi[4] = {0.f,0.f,0.f,0.f};
    #pragma unroll
    for (int np=0; np<4; np++){
        uint32_t aK[4];
        ldsm4(aK, sb + C_KS + (uint32_t)((lane&15)*KS + p0 + np*16 + (lane>>4)*8)*2);
        uint32_t bl[2], bh[2];
        bl[0] = packh2(relu6f(acc[2*np][0]*i0+e0),   relu6f(acc[2*np][1]*i0+e0));
        bl[1] = packh2(relu6f(acc[2*np+1][0]*i0+e0), relu6f(acc[2*np+1][1]*i0+e0));
        bh[0] = packh2(relu6f(acc[2*np][2]*i1+e1),   relu6f(acc[2*np][3]*i1+e1));
        bh[1] = packh2(relu6f(acc[2*np+1][2]*i1+e1), relu6f(acc[2*np+1][3]*i1+e1));
        mma16816h(d2lo, aK, bl);
        mma16816h(d2hi, aK, bh);
    }
    float* kvb = g_KV + b*MM*CC + g*CC;
    atomicAdd(kvb + m0 + t2,       d2lo[0]);
    atomicAdd(kvb + m0 + t2 + 1,   d2lo[1]);
    atomicAdd(kvb + m0+8 + t2,     d2hi[0]);
    atomicAdd(kvb + m0+8 + t2 + 1, d2hi[1]);
}

// ---------------------------------------------------------------------------
// K5: out = x + gamma * (Qt . KV) * norm.
// 2 px/thread (float2), 2-way channel split.
// ---------------------------------------------------------------------------
__global__ __launch_bounds__(256) void k_out(
    const float* __restrict__ x, const float* __restrict__ gamma,
    float* __restrict__ out)
{
    __shared__ __align__(16) float s_kv[MM*32];
    __shared__ float s_ks[MM];
    int tid = threadIdx.x;
    int p2 = (blockIdx.x*256 + tid)*2;
    int b = p2/NN, n = p2%NN;     // 512 | NN -> b block-uniform
    int co = blockIdx.y*32;

    if (tid < MM*32){
        int m = tid>>5, j = tid&31;
        s_kv[tid] = g_KV[b*MM*CC + m*CC + co + j];
    }
    if (tid<MM) s_ks[tid] = g_Ksum[b*MM+tid] + 1e-6f;
    __syncthreads();

    float2 q[MM];
    #pragma unroll
    for (int m=0;m<MM;m++)
        q[m] = *(const float2*)(g_Q + (size_t)b*MM*NN + (size_t)m*NN + n);

    float dx=0.f, dy=0.f;
    #pragma unroll
    for (int m=0;m<MM;m++){
        float ks = s_ks[m];
        dx = fmaf(q[m].x, ks, dx);
        dy = fmaf(q[m].y, ks, dy);
    }
    float gm = gamma[0];
    float gsx = gm/dx, gsy = gm/dy;

    const float* xb = x + (size_t)b*CC*NN + (size_t)co*NN + n;
    float* ob = out + (size_t)b*CC*NN + (size_t)co*NN + n;

    #pragma unroll 8
    for (int c=0;c<32;c++){
        float ax=0.f, ay=0.f;
        #pragma unroll
        for (int m=0;m<MM;m++){
            float wv = s_kv[m*32 + c];
            ax = fmaf(q[m].x, wv, ax);
            ay = fmaf(q[m].y, wv, ay);
        }
        float2 xv = *(const float2*)(xb + (size_t)c*NN);
        xv.x = fmaf(gsx, ax, xv.x);
        xv.y = fmaf(gsy, ay, xv.y);
        *(float2*)(ob + (size_t)c*NN) = xv;
    }
}

// ---------------------------------------------------------------------------
extern "C" void kernel_launch(void* const* d_in, const int* in_sizes, int n_in,
                              void* d_out, int out_size)
{
    const float* x      = (const float*)d_in[0];
    const float* gamma  = (const float*)d_in[1];
    const float* q_w    = (const float*)d_in[2];
    const float* q_b    = (const float*)d_in[3];
    const float* k_w    = (const float*)d_in[4];
    const float* k_b    = (const float*)d_in[5];
    const float* v_w    = (const float*)d_in[6];
    const float* v_b    = (const float*)d_in[7];
    const float* fc1_w  = (const float*)d_in[8];
    const float* fc1_bn = (const float*)d_in[9];
    const float* c1_w   = (const float*)d_in[10];
    const float* c1_bn  = (const float*)d_in[11];
    const float* c2_w   = (const float*)d_in[12];
    const float* c2_bn  = (const float*)d_in[13];
    const float* fc2_w  = (const float*)d_in[14];
    const float* fc2_bn = (const float*)d_in[15];
    float* out = (float*)d_out;

    cudaFuncSetAttribute(k_front,  cudaFuncAttributeMaxDynamicSharedMemorySize, F_SMEM);
    cudaFuncSetAttribute(k_fc2kv,  cudaFuncAttributeMaxDynamicSharedMemorySize, C_SMEM);

    k_zero<<<8,256>>>();
    k_front<<<dim3(NN/TPX,BB),288,F_SMEM>>>(x,q_w,q_b,k_w,k_b,v_w,v_b,fc1_w,fc1_bn);
    k_dw<<<dim3(WW/32,HH/16,BB*CC),dim3(16,16)>>>(c1_w,c1_bn,c2_w,c2_bn);
    k_fc2kv<<<dim3(NN/TPX,BB),256,C_SMEM>>>(fc2_w,fc2_bn);
    k_out<<<dim3(BN/512,2),256>>>(x,gamma,out);
}

// round 14
// speedup vs baseline: 1.0473x; 1.0473x over previous
#include <cuda_runtime.h>
#include <cuda_fp16.h>
#include <math.h>
#include <stdint.h>

#define BB 4
#define CC 64
#define MM 8
#define HH 224
#define WW 224
#define NN (HH*WW)      // 50176
#define BN (BB*NN)      // 200704
#define TPX 128         // pixels per CTA tile

// Scratch (static device globals — allocation-free per harness rules)
__device__ __half g_h[BB*CC*NN];
__device__ __half g_s[BB*CC*NN];
__device__ float g_Q[BB*MM*NN];
__device__ __half g_K[BB*MM*NN];
__device__ float g_KV[BB*MM*CC];
__device__ float g_Ksum[BB*MM];

__device__ __forceinline__ float relu6f(float x){ return fminf(fmaxf(x,0.f),6.f); }
__device__ __forceinline__ float softplusf(float x){
    return fmaxf(x,0.f) + __logf(1.f + __expf(-fabsf(x)));
}
__device__ __forceinline__ uint32_t smem_u32(const void* p){
    uint32_t a;
    asm("{ .reg .u64 t; cvta.to.shared.u64 t, %1; cvt.u32.u64 %0, t; }" : "=r"(a) : "l"(p));
    return a;
}
__device__ __forceinline__ uint32_t packh2(float a, float b){
    half2 h = __floats2half2_rn(a, b);
    return *(uint32_t*)&h;
}
__device__ __forceinline__ void ldsm4(uint32_t* r, uint32_t a){
    asm volatile("ldmatrix.sync.aligned.m8n8.x4.shared.b16 {%0,%1,%2,%3}, [%4];"
        : "=r"(r[0]),"=r"(r[1]),"=r"(r[2]),"=r"(r[3]) : "r"(a));
}
__device__ __forceinline__ void ldsm4t(uint32_t* r, uint32_t a){
    asm volatile("ldmatrix.sync.aligned.m8n8.x4.trans.shared.b16 {%0,%1,%2,%3}, [%4];"
        : "=r"(r[0]),"=r"(r[1]),"=r"(r[2]),"=r"(r[3]) : "r"(a));
}
__device__ __forceinline__ void mma16816h(float* d, const uint32_t* a, const uint32_t* b){
    asm volatile("mma.sync.aligned.m16n8k16.row.col.f32.f16.f16.f32 "
        "{%0,%1,%2,%3}, {%4,%5,%6,%7}, {%8,%9}, {%0,%1,%2,%3};"
        : "+f"(d[0]),"+f"(d[1]),"+f"(d[2]),"+f"(d[3])
        : "r"(a[0]),"r"(a[1]),"r"(a[2]),"r"(a[3]), "r"(b[0]),"r"(b[1]));
}

__global__ void k_zero(){
    int i = blockIdx.x*blockDim.x + threadIdx.x;
    if (i < BB*MM*CC) g_KV[i]   = 0.f;
    if (i < BB*MM)    g_Ksum[i] = 0.f;
}

// ---------------------------------------------------------------------------
// K1 front (fp16 mma.sync): D[144 out, 128 px] = W[144,64] x Xt[64,128]
// outputs: [v(0..63) | fc1(64..127) | q(128..135) | k(136..143)]
// 288 threads = 9 warps. KV-partial via 2nd MMA on V fragments (K staged f16).
// (unchanged from R12 — the GEMM2 epilogue won here)
// ---------------------------------------------------------------------------
#define F_WH  0
#define F_XH  20736
#define F_KS  20736     // alias of XH after mainloop: [16][136] f16 (rows 8-15 zero)
#define F_CST 38144
#define F_SMEM 38976
#define WS 72     // weight smem row stride (f16 elems)
#define XS 136    // x smem row stride (f16 elems)
#define KS 136    // K_s row stride (f16 elems)

__global__ __launch_bounds__(288,2) void k_front(
    const float* __restrict__ x,
    const float* __restrict__ q_w, const float* __restrict__ q_b,
    const float* __restrict__ k_w, const float* __restrict__ k_b,
    const float* __restrict__ v_w, const float* __restrict__ v_b,
    const float* __restrict__ fc1_w, const float* __restrict__ fc1_bn)
{
    extern __shared__ char sm[];
    __half* wH = (__half*)(sm + F_WH);
    __half* xH = (__half*)(sm + F_XH);
    __half* K_s = (__half*)(sm + F_KS);
    float* s_vb   = (float*)(sm + F_CST);         // 64
    float* s_finv = s_vb + 64;                    // 64
    float* s_fbeta= s_finv + 64;                  // 64
    float* s_qb   = s_fbeta + 64;                 // 8
    float* s_kb   = s_qb + 8;                     // 8
    uint32_t sb = smem_u32(sm);

    int tid = threadIdx.x;
    int b  = blockIdx.y;
    int n0 = blockIdx.x * TPX;

    // weights: 144 x 64 -> fp16
    for (int i=tid; i<144*32; i+=288){
        int o = i>>5, c2 = (i&31)<<1;
        const float* src = (o<64) ? v_w + o*64
                         : (o<128)? fc1_w + (o-64)*64
                         : (o<136)? q_w + (o-128)*64
                         :          k_w + (o-136)*64;
        *(half2*)(wH + o*WS + c2) = __floats2half2_rn(src[c2], src[c2+1]);
    }
    // x tile: [64 ch][128 px] -> fp16
    const float* xb = x + (size_t)b*CC*NN + n0;
    for (int i=tid; i<64*64; i+=288){
        int c = i>>6, p2 = (i&63)<<1;
        float2 v = *(const float2*)(xb + (size_t)c*NN + p2);
        *(half2*)(xH + c*XS + p2) = __floats2half2_rn(v.x, v.y);
    }
    if (tid < 64){
        s_vb[tid] = v_b[tid];
        float sc=fc1_bn[0*CC+tid], bi=fc1_bn[1*CC+tid];
        float mn=fc1_bn[2*CC+tid], vr=fc1_bn[3*CC+tid];
        float inv = sc*rsqrtf(vr+1e-5f);
        s_finv[tid]=inv; s_fbeta[tid]=bi-mn*inv;
    } else if (tid < 72){
        s_qb[tid-64] = q_b[tid-64];
        s_kb[tid-64] = k_b[tid-64];
    }
    __syncthreads();

    int w = tid >> 5, lane = tid & 31;
    int m0 = w*16;

    float acc[16][4];
    #pragma unroll
    for (int i=0;i<16;i++){ acc[i][0]=acc[i][1]=acc[i][2]=acc[i][3]=0.f; }

    int arow = m0 + (lane & 15), acol8 = (lane>>4)*8;
    int brow = (lane & 7) + 8*((lane>>3)&1), bcol8 = (lane>>4)*8;

    #pragma unroll
    for (int kt=0; kt<4; kt++){
        int k0 = kt*16;
        uint32_t a[4];
        ldsm4(a, sb + F_WH + (uint32_t)(arow*WS + k0 + acol8)*2);
        #pragma unroll
        for (int np=0; np<8; np++){
            uint32_t bF[4];
            ldsm4t(bF, sb + F_XH + (uint32_t)((k0+brow)*XS + np*16 + bcol8)*2);
            mma16816h(acc[2*np],   a, bF);
            mma16816h(acc[2*np+1], a, bF+2);
        }
    }

    __syncthreads();   // sync1: mainloop smem reads done -> K_s alias safe

    int g = lane >> 2, t2 = (lane & 3)*2;
    if (w < 4){
        // zero pad K_s rows 8..15 (2 rows per warp)
        int r0 = 8 + 2*w;
        for (int j=lane; j<KS; j+=32){
            K_s[r0*KS + j]     = __float2half(0.f);
            K_s[(r0+1)*KS + j] = __float2half(0.f);
        }
    } else if (w < 8){
        int o0 = m0 - 64 + g, o1 = o0 + 8;
        float i0=s_finv[o0], e0=s_fbeta[o0], i1=s_finv[o1], e1=s_fbeta[o1];
        __half* p0 = g_h + ((size_t)b*CC + o0)*NN + n0 + t2;
        __half* p1 = g_h + ((size_t)b*CC + o1)*NN + n0 + t2;
        #pragma unroll
        for (int nt=0; nt<16; nt++){
            *(half2*)(p0 + nt*8) = __floats2half2_rn(relu6f(acc[nt][0]*i0+e0), relu6f(acc[nt][1]*i0+e0));
            *(half2*)(p1 + nt*8) = __floats2half2_rn(relu6f(acc[nt][2]*i1+e1), relu6f(acc[nt][3]*i1+e1));
        }
    } else {
        // rows g -> Q[m=g], rows g+8 -> K[m=g]
        float bq = s_qb[g], bk = s_kb[g];
        float*  pq = g_Q + ((size_t)b*MM + g)*NN + n0 + t2;
        __half* pk = g_K + ((size_t)b*MM + g)*NN + n0 + t2;
        float ksum = 0.f;
        #pragma unroll
        for (int nt=0; nt<16; nt++){
            int px = nt*8 + t2;
            float q0 = softplusf(acc[nt][0]+bq), q1 = softplusf(acc[nt][1]+bq);
            float k0v = softplusf(acc[nt][2]+bk), k1v = softplusf(acc[nt][3]+bk);
            *(float2*)(pq + nt*8) = make_float2(q0, q1);
            half2 kk = __floats2half2_rn(k0v, k1v);
            *(half2*)(pk + nt*8) = kk;
            *(half2*)(K_s + g*KS + px) = kk;
            ksum += k0v + k1v;
        }
        ksum += __shfl_xor_sync(0xffffffffu, ksum, 1);
        ksum += __shfl_xor_sync(0xffffffffu, ksum, 2);
        if ((lane & 3) == 0) atomicAdd(&g_Ksum[b*MM + g], ksum);
    }
    __syncthreads();   // sync2: K_s ready

    // GEMM2: KV[m, ch] += sum_px K[m,px] * (Vconv[ch,px]+vb[ch])  (warps 0..3)
    if (w < 4){
        float vb0 = s_vb[m0+g], vb1 = s_vb[m0+8+g];
        float d2lo[4] = {0.f,0.f,0.f,0.f}, d2hi[4] = {0.f,0.f,0.f,0.f};
        #pragma unroll
        for (int np=0; np<8; np++){
            uint32_t aK[4];
            ldsm4(aK, sb + F_KS + (uint32_t)((lane&15)*KS + np*16 + (lane>>4)*8)*2);
            uint32_t bl[2], bh[2];
            bl[0] = packh2(acc[2*np][0]+vb0,   acc[2*np][1]+vb0);
            bl[1] = packh2(acc[2*np+1][0]+vb0, acc[2*np+1][1]+vb0);
            bh[0] = packh2(acc[2*np][2]+vb1,   acc[2*np][3]+vb1);
            bh[1] = packh2(acc[2*np+1][2]+vb1, acc[2*np+1][3]+vb1);
            mma16816h(d2lo, aK, bl);
            mma16816h(d2hi, aK, bh);
        }
        float* kvb = g_KV + b*MM*CC + g*CC;
        atomicAdd(kvb + m0 + t2,       d2lo[0]);
        atomicAdd(kvb + m0 + t2 + 1,   d2lo[1]);
        atomicAdd(kvb + m0+8 + t2,     d2hi[0]);
        atomicAdd(kvb + m0+8 + t2 + 1, d2hi[1]);
    }
}

// ---------------------------------------------------------------------------
// K2: depthwise 5x5 + 3x3 (both BN+ReLU6), summed -> g_s (fp16 in/out)
// ---------------------------------------------------------------------------
__global__ __launch_bounds__(256) void k_dw(
    const float* __restrict__ w5, const float* __restrict__ bn5,
    const float* __restrict__ w3, const float* __restrict__ bn3)
{
    int bc = blockIdx.z;
    int c  = bc & (CC-1);
    int y0 = blockIdx.y*16, x0 = blockIdx.x*32;

    __shared__ float t[20][36];
    __shared__ float s_w5[25], s_w3[9], s_c[4];

    int tid = threadIdx.y*16 + threadIdx.x;
    const __half* plane = g_h + (size_t)bc*NN;

    for (int i=tid;i<20*36;i+=256){
        int ly=i/36, lx=i%36;
        int gy=y0+ly-2, gx=x0+lx-2;
        float v = 0.f;
        if (gy>=0 && gy<HH && gx>=0 && gx<WW) v = __half2float(plane[gy*WW+gx]);
        t[ly][lx] = v;
    }
    if (tid<25) s_w5[tid] = w5[c*25+tid];
    if (tid<9)  s_w3[tid] = w3[c*9+tid];
    if (tid==0){
        float inv = bn5[0*CC+c]*rsqrtf(bn5[3*CC+c]+1e-5f);
        s_c[0]=inv; s_c[1]=bn5[1*CC+c]-bn5[2*CC+c]*inv;
    }
    if (tid==32){
        float inv = bn3[0*CC+c]*rsqrtf(bn3[3*CC+c]+1e-5f);
        s_c[2]=inv; s_c[3]=bn3[1*CC+c]-bn3[2*CC+c]*inv;
    }
    __syncthreads();

    int ty = threadIdx.y;        // 0..15 (row)
    int tx2 = threadIdx.x*2;     // 0,2,..,30 (2 px per thread)

    float a5a=0.f, a5b=0.f;
    #pragma unroll
    for (int i=0;i<5;i++){
        const float* r = &t[ty+i][tx2];
        float c0=r[0], c1=r[1], c2=r[2], c3=r[3], c4=r[4], c5=r[5];
        float w0=s_w5[i*5], w1=s_w5[i*5+1], w2=s_w5[i*5+2], w3v=s_w5[i*5+3], w4=s_w5[i*5+4];
        a5a = fmaf(w0,c0, fmaf(w1,c1, fmaf(w2,c2, fmaf(w3v,c3, fmaf(w4,c4, a5a)))));
        a5b = fmaf(w0,c1, fmaf(w1,c2, fmaf(w2,c3, fmaf(w3v,c4, fmaf(w4,c5, a5b)))));
    }
    float a3a=0.f, a3b=0.f;
    #pragma unroll
    for (int i=0;i<3;i++){
        const float* r = &t[ty+1+i][tx2+1];
        float c0=r[0], c1=r[1], c2=r[2], c3=r[3];
        float w0=s_w3[i*3], w1=s_w3[i*3+1], w2=s_w3[i*3+2];
        a3a = fmaf(w0,c0, fmaf(w1,c1, fmaf(w2,c2, a3a)));
        a3b = fmaf(w0,c1, fmaf(w1,c2, fmaf(w2,c3, a3b)));
    }

    float ra = relu6f(a5a*s_c[0]+s_c[1]) + relu6f(a3a*s_c[2]+s_c[3]);
    float rb = relu6f(a5b*s_c[0]+s_c[1]) + relu6f(a3b*s_c[2]+s_c[3]);
    *(half2*)(g_s + (size_t)bc*NN + (y0+ty)*WW + (x0+tx2)) = __floats2half2_rn(ra, rb);
}

// ---------------------------------------------------------------------------
// K3: fc2 (fp16 mma.sync) + fused KV of xc via smem reduce (R10/R11 epilogue,
// reverted — fragment-GEMM2 doubled atomic contention here and regressed).
// smem bytes: AH 0 (9216), XH 9216 (17408); v_s alias 0..33280;
//             KT 33280 (4096 f32), INV 37376, BETA 37632 -> 37888
// ---------------------------------------------------------------------------
#define C_AH  0
#define C_XH  9216
#define C_VS  0
#define C_KT  33280
#define C_INV 37376
#define C_BETA 37632
#define C_SMEM 37888

__global__ __launch_bounds__(256,4) void k_fc2kv(
    const float* __restrict__ fc2_w, const float* __restrict__ fc2_bn)
{
    extern __shared__ char sm[];
    __half* aH = (__half*)(sm + C_AH);
    __half* xH = (__half*)(sm + C_XH);
    float* s_K   = (float*)(sm + C_KT);
    float* s_inv = (float*)(sm + C_INV);
    float* s_beta= (float*)(sm + C_BETA);
    float* v_s   = (float*)(sm + C_VS);   // alias, used after mainloop
    uint32_t sb = smem_u32(sm);

    int tid = threadIdx.x;
    int b  = blockIdx.y;
    int n0 = blockIdx.x * TPX;

    // weights 64x64 -> fp16
    for (int i=tid; i<64*32; i+=256){
        int o = i>>5, c2 = (i&31)<<1;
        *(half2*)(aH + o*WS + c2) = __floats2half2_rn(fc2_w[o*64+c2], fc2_w[o*64+c2+1]);
    }
    // s tile [64 ch][128 px] — raw fp16 copy
    const __half* sp = g_s + (size_t)b*CC*NN + n0;
    for (int i=tid; i<64*16; i+=256){
        int c = i>>4, p8 = (i&15)<<3;
        *(uint4*)(xH + c*XS + p8) = *(const uint4*)(sp + (size_t)c*NN + p8);
    }
    // K tile [8][128]: fp16 gmem -> f32 smem
    {
        const __half* kp = g_K + (size_t)b*MM*NN + n0;
        int m = tid >> 5, p8 = (tid & 31)*4;   // 4 halves per thread x 32 = 128
        half2 k01 = *(const half2*)(kp + (size_t)m*NN + p8);
        half2 k23 = *(const half2*)(kp + (size_t)m*NN + p8 + 2);
        float2 f01 = __half22float2(k01), f23 = __half22float2(k23);
        float* kr = s_K + m*TPX + p8;
        kr[0]=f01.x; kr[1]=f01.y; kr[2]=f23.x; kr[3]=f23.y;
    }
    if (tid < 64){
        float sc=fc2_bn[0*CC+tid], bi=fc2_bn[1*CC+tid];
        float mn=fc2_bn[2*CC+tid], vr=fc2_bn[3*CC+tid];
        float inv = sc*rsqrtf(vr+1e-5f);
        s_inv[tid]=inv; s_beta[tid]=bi-mn*inv;
    }
    __syncthreads();

    int w = tid >> 5, lane = tid & 31;
    int mt = w & 3, ph = w >> 2;
    int m0 = mt*16, p0 = ph*64;

    float acc[8][4];
    #pragma unroll
    for (int i=0;i<8;i++){ acc[i][0]=acc[i][1]=acc[i][2]=acc[i][3]=0.f; }

    int arow = m0 + (lane & 15), acol8 = (lane>>4)*8;
    int brow = (lane & 7) + 8*((lane>>3)&1), bcol8 = (lane>>4)*8;

    #pragma unroll
    for (int kt=0; kt<4; kt++){
        int k0 = kt*16;
        uint32_t a[4];
        ldsm4(a, sb + C_AH + (uint32_t)(arow*WS + k0 + acol8)*2);
        #pragma unroll
        for (int np=0; np<4; np++){
            uint32_t bF[4];
            ldsm4t(bF, sb + C_XH + (uint32_t)((k0+brow)*XS + p0 + np*16 + bcol8)*2);
            mma16816h(acc[2*np],   a, bF);
            mma16816h(acc[2*np+1], a, bF+2);
        }
    }

    __syncthreads();   // everyone done reading xH -> reuse as v_s

    // epilogue: xc = relu6(bn(D)) -> smem directly
    int g = lane >> 2, t2 = (lane & 3)*2;
    int o0 = m0 + g, o1 = o0 + 8;
    float i0 = s_inv[o0], e0 = s_beta[o0], i1 = s_inv[o1], e1 = s_beta[o1];
    #pragma unroll
    for (int nt=0; nt<8; nt++){
        int px = p0 + nt*8 + t2;
        v_s[ px   *65 + o0] = relu6f(acc[nt][0]*i0+e0);
        v_s[(px+1)*65 + o0] = relu6f(acc[nt][1]*i0+e0);
        v_s[ px   *65 + o1] = relu6f(acc[nt][2]*i1+e1);
        v_s[(px+1)*65 + o1] = relu6f(acc[nt][3]*i1+e1);
    }
    __syncthreads();

    // KV reduction over xc (split chains)
    {
        int m = tid >> 6, c = tid & 63;
        const float* k0r = s_K + m*TPX;
        const float* k1r = s_K + (m+4)*TPX;
        float a0=0.f, a1=0.f, c0=0.f, c1=0.f;
        #pragma unroll 8
        for (int p=0;p<TPX/2;p++){
            float v = v_s[p*65 + c];
            a0 = fmaf(k0r[p], v, a0);
            a1 = fmaf(k1r[p], v, a1);
        }
        #pragma unroll 8
        for (int p=TPX/2;p<TPX;p++){
            float v = v_s[p*65 + c];
            c0 = fmaf(k0r[p], v, c0);
            c1 = fmaf(k1r[p], v, c1);
        }
        atomicAdd(&g_KV[b*MM*CC + m*CC     + c], a0+c0);
        atomicAdd(&g_KV[b*MM*CC + (m+4)*CC + c], a1+c1);
    }
}

// ---------------------------------------------------------------------------
// K5: out = x + gamma * (Qt . KV) * norm.
// 2 px/thread (float2), 2-way channel split.
// ---------------------------------------------------------------------------
__global__ __launch_bounds__(256) void k_out(
    const float* __restrict__ x, const float* __restrict__ gamma,
    float* __restrict__ out)
{
    __shared__ __align__(16) float s_kv[MM*32];
    __shared__ float s_ks[MM];
    int tid = threadIdx.x;
    int p2 = (blockIdx.x*256 + tid)*2;
    int b = p2/NN, n = p2%NN;     // 512 | NN -> b block-uniform
    int co = blockIdx.y*32;

    if (tid < MM*32){
        int m = tid>>5, j = tid&31;
        s_kv[tid] = g_KV[b*MM*CC + m*CC + co + j];
    }
    if (tid<MM) s_ks[tid] = g_Ksum[b*MM+tid] + 1e-6f;
    __syncthreads();

    float2 q[MM];
    #pragma unroll
    for (int m=0;m<MM;m++)
        q[m] = *(const float2*)(g_Q + (size_t)b*MM*NN + (size_t)m*NN + n);

    float dx=0.f, dy=0.f;
    #pragma unroll
    for (int m=0;m<MM;m++){
        float ks = s_ks[m];
        dx = fmaf(q[m].x, ks, dx);
        dy = fmaf(q[m].y, ks, dy);
    }
    float gm = gamma[0];
    float gsx = gm/dx, gsy = gm/dy;

    const float* xb = x + (size_t)b*CC*NN + (size_t)co*NN + n;
    float* ob = out + (size_t)b*CC*NN + (size_t)co*NN + n;

    #pragma unroll 8
    for (int c=0;c<32;c++){
        float ax=0.f, ay=0.f;
        #pragma unroll
        for (int m=0;m<MM;m++){
            float wv = s_kv[m*32 + c];
            ax = fmaf(q[m].x, wv, ax);
            ay = fmaf(q[m].y, wv, ay);
        }
        float2 xv = *(const float2*)(xb + (size_t)c*NN);
        xv.x = fmaf(gsx, ax, xv.x);
        xv.y = fmaf(gsy, ay, xv.y);
        *(float2*)(ob + (size_t)c*NN) = xv;
    }
}

// ---------------------------------------------------------------------------
extern "C" void kernel_launch(void* const* d_in, const int* in_sizes, int n_in,
                              void* d_out, int out_size)
{
    const float* x      = (const float*)d_in[0];
    const float* gamma  = (const float*)d_in[1];
    const float* q_w    = (const float*)d_in[2];
    const float* q_b    = (const float*)d_in[3];
    const float* k_w    = (const float*)d_in[4];
    const float* k_b    = (const float*)d_in[5];
    const float* v_w    = (const float*)d_in[6];
    const float* v_b    = (const float*)d_in[7];
    const float* fc1_w  = (const float*)d_in[8];
    const float* fc1_bn = (const float*)d_in[9];
    const float* c1_w   = (const float*)d_in[10];
    const float* c1_bn  = (const float*)d_in[11];
    const float* c2_w   = (const float*)d_in[12];
    const float* c2_bn  = (const float*)d_in[13];
    const float* fc2_w  = (const float*)d_in[14];
    const float* fc2_bn = (const float*)d_in[15];
    float* out = (float*)d_out;

    cudaFuncSetAttribute(k_front,  cudaFuncAttributeMaxDynamicSharedMemorySize, F_SMEM);
    cudaFuncSetAttribute(k_fc2kv,  cudaFuncAttributeMaxDynamicSharedMemorySize, C_SMEM);

    k_zero<<<8,256>>>();
    k_front<<<dim3(NN/TPX,BB),288,F_SMEM>>>(x,q_w,q_b,k_w,k_b,v_w,v_b,fc1_w,fc1_bn);
    k_dw<<<dim3(WW/32,HH/16,BB*CC),dim3(16,16)>>>(c1_w,c1_bn,c2_w,c2_bn);
    k_fc2kv<<<dim3(NN/TPX,BB),256,C_SMEM>>>(fc2_w,fc2_bn);
    k_out<<<dim3(BN/512,2),256>>>(x,gamma,out);
}

// round 15
// speedup vs baseline: 1.0823x; 1.0334x over previous
#include <cuda_runtime.h>
#include <cuda_fp16.h>
#include <math.h>
#include <stdint.h>

#define BB 4
#define CC 64
#define MM 8
#define HH 224
#define WW 224
#define NN (HH*WW)      // 50176
#define BN (BB*NN)      // 200704
#define TPX 128         // pixels per CTA tile

// Scratch (static device globals — allocation-free per harness rules)
__device__ __half g_h[BB*CC*NN];
__device__ __half g_s[BB*CC*NN];
__device__ __half g_Q[BB*MM*NN];
__device__ __half g_K[BB*MM*NN];
__device__ float g_KV[BB*MM*CC];
__device__ float g_Ksum[BB*MM];

__device__ __forceinline__ float relu6f(float x){ return fminf(fmaxf(x,0.f),6.f); }
__device__ __forceinline__ float softplusf(float x){
    return fmaxf(x,0.f) + __logf(1.f + __expf(-fabsf(x)));
}
__device__ __forceinline__ uint32_t smem_u32(const void* p){
    uint32_t a;
    asm("{ .reg .u64 t; cvta.to.shared.u64 t, %1; cvt.u32.u64 %0, t; }" : "=r"(a) : "l"(p));
    return a;
}
__device__ __forceinline__ uint32_t packh2(float a, float b){
    half2 h = __floats2half2_rn(a, b);
    return *(uint32_t*)&h;
}
__device__ __forceinline__ void ldsm4(uint32_t* r, uint32_t a){
    asm volatile("ldmatrix.sync.aligned.m8n8.x4.shared.b16 {%0,%1,%2,%3}, [%4];"
        : "=r"(r[0]),"=r"(r[1]),"=r"(r[2]),"=r"(r[3]) : "r"(a));
}
__device__ __forceinline__ void ldsm4t(uint32_t* r, uint32_t a){
    asm volatile("ldmatrix.sync.aligned.m8n8.x4.trans.shared.b16 {%0,%1,%2,%3}, [%4];"
        : "=r"(r[0]),"=r"(r[1]),"=r"(r[2]),"=r"(r[3]) : "r"(a));
}
__device__ __forceinline__ void mma16816h(float* d, const uint32_t* a, const uint32_t* b){
    asm volatile("mma.sync.aligned.m16n8k16.row.col.f32.f16.f16.f32 "
        "{%0,%1,%2,%3}, {%4,%5,%6,%7}, {%8,%9}, {%0,%1,%2,%3};"
        : "+f"(d[0]),"+f"(d[1]),"+f"(d[2]),"+f"(d[3])
        : "r"(a[0]),"r"(a[1]),"r"(a[2]),"r"(a[3]), "r"(b[0]),"r"(b[1]));
}

__global__ void k_zero(){
    int i = blockIdx.x*blockDim.x + threadIdx.x;
    if (i < BB*MM*CC) g_KV[i]   = 0.f;
    if (i < BB*MM)    g_Ksum[i] = 0.f;
}

// ---------------------------------------------------------------------------
// K1 front (fp16 mma.sync): D[144 out, 128 px] = W[144,64] x Xt[64,128]
// outputs: [v(0..63) | fc1(64..127) | q(128..135) | k(136..143)]
// 288 threads = 9 warps. KV-partial via 2nd MMA on V fragments (K staged f16).
// ---------------------------------------------------------------------------
#define F_WH  0
#define F_XH  20736
#define F_KS  20736     // alias of XH after mainloop: [16][136] f16 (rows 8-15 zero)
#define F_CST 38144
#define F_SMEM 38976
#define WS 72     // weight smem row stride (f16 elems)
#define XS 136    // x smem row stride (f16 elems)
#define KS 136    // K_s row stride (f16 elems)

__global__ __launch_bounds__(288,2) void k_front(
    const float* __restrict__ x,
    const float* __restrict__ q_w, const float* __restrict__ q_b,
    const float* __restrict__ k_w, const float* __restrict__ k_b,
    const float* __restrict__ v_w, const float* __restrict__ v_b,
    const float* __restrict__ fc1_w, const float* __restrict__ fc1_bn)
{
    extern __shared__ char sm[];
    __half* wH = (__half*)(sm + F_WH);
    __half* xH = (__half*)(sm + F_XH);
    __half* K_s = (__half*)(sm + F_KS);
    float* s_vb   = (float*)(sm + F_CST);         // 64
    float* s_finv = s_vb + 64;                    // 64
    float* s_fbeta= s_finv + 64;                  // 64
    float* s_qb   = s_fbeta + 64;                 // 8
    float* s_kb   = s_qb + 8;                     // 8
    uint32_t sb = smem_u32(sm);

    int tid = threadIdx.x;
    int b  = blockIdx.y;
    int n0 = blockIdx.x * TPX;

    // weights: 144 x 64 -> fp16
    for (int i=tid; i<144*32; i+=288){
        int o = i>>5, c2 = (i&31)<<1;
        const float* src = (o<64) ? v_w + o*64
                         : (o<128)? fc1_w + (o-64)*64
                         : (o<136)? q_w + (o-128)*64
                         :          k_w + (o-136)*64;
        *(half2*)(wH + o*WS + c2) = __floats2half2_rn(src[c2], src[c2+1]);
    }
    // x tile: [64 ch][128 px] -> fp16
    const float* xb = x + (size_t)b*CC*NN + n0;
    for (int i=tid; i<64*64; i+=288){
        int c = i>>6, p2 = (i&63)<<1;
        float2 v = *(const float2*)(xb + (size_t)c*NN + p2);
        *(half2*)(xH + c*XS + p2) = __floats2half2_rn(v.x, v.y);
    }
    if (tid < 64){
        s_vb[tid] = v_b[tid];
        float sc=fc1_bn[0*CC+tid], bi=fc1_bn[1*CC+tid];
        float mn=fc1_bn[2*CC+tid], vr=fc1_bn[3*CC+tid];
        float inv = sc*rsqrtf(vr+1e-5f);
        s_finv[tid]=inv; s_fbeta[tid]=bi-mn*inv;
    } else if (tid < 72){
        s_qb[tid-64] = q_b[tid-64];
        s_kb[tid-64] = k_b[tid-64];
    }
    __syncthreads();

    int w = tid >> 5, lane = tid & 31;
    int m0 = w*16;

    float acc[16][4];
    #pragma unroll
    for (int i=0;i<16;i++){ acc[i][0]=acc[i][1]=acc[i][2]=acc[i][3]=0.f; }

    int arow = m0 + (lane & 15), acol8 = (lane>>4)*8;
    int brow = (lane & 7) + 8*((lane>>3)&1), bcol8 = (lane>>4)*8;

    #pragma unroll
    for (int kt=0; kt<4; kt++){
        int k0 = kt*16;
        uint32_t a[4];
        ldsm4(a, sb + F_WH + (uint32_t)(arow*WS + k0 + acol8)*2);
        #pragma unroll
        for (int np=0; np<8; np++){
            uint32_t bF[4];
            ldsm4t(bF, sb + F_XH + (uint32_t)((k0+brow)*XS + np*16 + bcol8)*2);
            mma16816h(acc[2*np],   a, bF);
            mma16816h(acc[2*np+1], a, bF+2);
        }
    }

    __syncthreads();   // sync1: mainloop smem reads done -> K_s alias safe

    int g = lane >> 2, t2 = (lane & 3)*2;
    if (w < 4){
        // zero pad K_s rows 8..15 (2 rows per warp)
        int r0 = 8 + 2*w;
        for (int j=lane; j<KS; j+=32){
            K_s[r0*KS + j]     = __ushort_as_half(0);
            K_s[(r0+1)*KS + j] = __ushort_as_half(0);
        }
    } else if (w < 8){
        int o0 = m0 - 64 + g, o1 = o0 + 8;
        float i0=s_finv[o0], e0=s_fbeta[o0], i1=s_finv[o1], e1=s_fbeta[o1];
        __half* p0 = g_h + ((size_t)b*CC + o0)*NN + n0 + t2;
        __half* p1 = g_h + ((size_t)b*CC + o1)*NN + n0 + t2;
        #pragma unroll
        for (int nt=0; nt<16; nt++){
            *(half2*)(p0 + nt*8) = __floats2half2_rn(relu6f(acc[nt][0]*i0+e0), relu6f(acc[nt][1]*i0+e0));
            *(half2*)(p1 + nt*8) = __floats2half2_rn(relu6f(acc[nt][2]*i1+e1), relu6f(acc[nt][3]*i1+e1));
        }
    } else {
        // rows g -> Q[m=g], rows g+8 -> K[m=g]
        float bq = s_qb[g], bk = s_kb[g];
        __half* pq = g_Q + ((size_t)b*MM + g)*NN + n0 + t2;
        __half* pk = g_K + ((size_t)b*MM + g)*NN + n0 + t2;
        float ksum = 0.f;
        #pragma unroll
        for (int nt=0; nt<16; nt++){
            int px = nt*8 + t2;
            float q0 = softplusf(acc[nt][0]+bq), q1 = softplusf(acc[nt][1]+bq);
            float k0v = softplusf(acc[nt][2]+bk), k1v = softplusf(acc[nt][3]+bk);
            *(half2*)(pq + nt*8) = __floats2half2_rn(q0, q1);
            half2 kk = __floats2half2_rn(k0v, k1v);
            *(half2*)(pk + nt*8) = kk;
            *(half2*)(K_s + g*KS + px) = kk;
            ksum += k0v + k1v;
        }
        ksum += __shfl_xor_sync(0xffffffffu, ksum, 1);
        ksum += __shfl_xor_sync(0xffffffffu, ksum, 2);
        if ((lane & 3) == 0) atomicAdd(&g_Ksum[b*MM + g], ksum);
    }
    __syncthreads();   // sync2: K_s ready

    // GEMM2: KV[m, ch] += sum_px K[m,px] * (Vconv[ch,px]+vb[ch])  (warps 0..3)
    if (w < 4){
        float vb0 = s_vb[m0+g], vb1 = s_vb[m0+8+g];
        float d2lo[4] = {0.f,0.f,0.f,0.f}, d2hi[4] = {0.f,0.f,0.f,0.f};
        #pragma unroll
        for (int np=0; np<8; np++){
            uint32_t aK[4];
            ldsm4(aK, sb + F_KS + (uint32_t)((lane&15)*KS + np*16 + (lane>>4)*8)*2);
            uint32_t bl[2], bh[2];
            bl[0] = packh2(acc[2*np][0]+vb0,   acc[2*np][1]+vb0);
            bl[1] = packh2(acc[2*np+1][0]+vb0, acc[2*np+1][1]+vb0);
            bh[0] = packh2(acc[2*np][2]+vb1,   acc[2*np][3]+vb1);
            bh[1] = packh2(acc[2*np+1][2]+vb1, acc[2*np+1][3]+vb1);
            mma16816h(d2lo, aK, bl);
            mma16816h(d2hi, aK, bh);
        }
        float* kvb = g_KV + b*MM*CC + g*CC;
        atomicAdd(kvb + m0 + t2,       d2lo[0]);
        atomicAdd(kvb + m0 + t2 + 1,   d2lo[1]);
        atomicAdd(kvb + m0+8 + t2,     d2hi[0]);
        atomicAdd(kvb + m0+8 + t2 + 1, d2hi[1]);
    }
}

// ---------------------------------------------------------------------------
// K2: depthwise 5x5 + 3x3 (both BN+ReLU6), summed -> g_s (fp16 in/out)
// HFMA2: 2 horizontal px per thread packed in half2. 3x3 reuses 5x5 pairs.
// ---------------------------------------------------------------------------
__global__ __launch_bounds__(256) void k_dw(
    const float* __restrict__ w5, const float* __restrict__ bn5,
    const float* __restrict__ w3, const float* __restrict__ bn3)
{
    int bc = blockIdx.z;
    int c  = bc & (CC-1);
    int y0 = blockIdx.y*16, x0 = blockIdx.x*32;

    __shared__ __half t[20][40];
    __shared__ __half2 s_w5[25], s_w3[9];
    __shared__ float s_c[4];

    int tid = threadIdx.y*16 + threadIdx.x;
    const __half* plane = g_h + (size_t)bc*NN;

    for (int i=tid;i<20*36;i+=256){
        int ly=i/36, lx=i%36;
        int gy=y0+ly-2, gx=x0+lx-2;
        __half v = __ushort_as_half(0);
        if (gy>=0 && gy<HH && gx>=0 && gx<WW) v = plane[gy*WW+gx];
        t[ly][lx] = v;
    }
    if (tid < 25)               s_w5[tid]    = __float2half2_rn(w5[c*25+tid]);
    if (tid >= 32 && tid < 41)  s_w3[tid-32] = __float2half2_rn(w3[c*9+tid-32]);
    if (tid == 64){
        float inv = bn5[0*CC+c]*rsqrtf(bn5[3*CC+c]+1e-5f);
        s_c[0]=inv; s_c[1]=bn5[1*CC+c]-bn5[2*CC+c]*inv;
    }
    if (tid == 80){
        float inv = bn3[0*CC+c]*rsqrtf(bn3[3*CC+c]+1e-5f);
        s_c[2]=inv; s_c[3]=bn3[1*CC+c]-bn3[2*CC+c]*inv;
    }
    __syncthreads();

    int ty = threadIdx.y;        // 0..15 (row)
    int tx2 = threadIdx.x*2;     // 0,2,..,30 (2 px per thread)

    __half2 acc5 = __float2half2_rn(0.f);
    __half2 acc3 = __float2half2_rn(0.f);
    #pragma unroll
    for (int i=0;i<5;i++){
        const __half2* r = (const __half2*)&t[ty+i][tx2];   // tx2 even -> 4B aligned
        __half2 A = r[0], B = r[1], C = r[2];               // cols {0,1},{2,3},{4,5}
        __half2 p1 = __halves2half2(__high2half(A), __low2half(B));  // {1,2}
        __half2 p3 = __halves2half2(__high2half(B), __low2half(C));  // {3,4}
        acc5 = __hfma2(A,  s_w5[i*5+0], acc5);
        acc5 = __hfma2(p1, s_w5[i*5+1], acc5);
        acc5 = __hfma2(B,  s_w5[i*5+2], acc5);
        acc5 = __hfma2(p3, s_w5[i*5+3], acc5);
        acc5 = __hfma2(C,  s_w5[i*5+4], acc5);
        if (i >= 1 && i <= 3){
            int j = i-1;
            acc3 = __hfma2(p1, s_w3[j*3+0], acc3);
            acc3 = __hfma2(B,  s_w3[j*3+1], acc3);
            acc3 = __hfma2(p3, s_w3[j*3+2], acc3);
        }
    }

    float2 a5 = __half22float2(acc5);
    float2 a3 = __half22float2(acc3);
    float ra = relu6f(a5.x*s_c[0]+s_c[1]) + relu6f(a3.x*s_c[2]+s_c[3]);
    float rb = relu6f(a5.y*s_c[0]+s_c[1]) + relu6f(a3.y*s_c[2]+s_c[3]);
    *(half2*)(g_s + (size_t)bc*NN + (y0+ty)*WW + (x0+tx2)) = __floats2half2_rn(ra, rb);
}

// ---------------------------------------------------------------------------
// K3: fc2 (fp16 mma.sync) + fused KV of xc via smem reduce.
// ---------------------------------------------------------------------------
#define C_AH  0
#define C_XH  9216
#define C_VS  0
#define C_KT  33280
#define C_INV 37376
#define C_BETA 37632
#define C_SMEM 37888

__global__ __launch_bounds__(256,4) void k_fc2kv(
    const float* __restrict__ fc2_w, const float* __restrict__ fc2_bn)
{
    extern __shared__ char sm[];
    __half* aH = (__half*)(sm + C_AH);
    __half* xH = (__half*)(sm + C_XH);
    float* s_K   = (float*)(sm + C_KT);
    float* s_inv = (float*)(sm + C_INV);
    float* s_beta= (float*)(sm + C_BETA);
    float* v_s   = (float*)(sm + C_VS);   // alias, used after mainloop
    uint32_t sb = smem_u32(sm);

    int tid = threadIdx.x;
    int b  = blockIdx.y;
    int n0 = blockIdx.x * TPX;

    // weights 64x64 -> fp16
    for (int i=tid; i<64*32; i+=256){
        int o = i>>5, c2 = (i&31)<<1;
        *(half2*)(aH + o*WS + c2) = __floats2half2_rn(fc2_w[o*64+c2], fc2_w[o*64+c2+1]);
    }
    // s tile [64 ch][128 px] — raw fp16 copy
    const __half* sp = g_s + (size_t)b*CC*NN + n0;
    for (int i=tid; i<64*16; i+=256){
        int c = i>>4, p8 = (i&15)<<3;
        *(uint4*)(xH + c*XS + p8) = *(const uint4*)(sp + (size_t)c*NN + p8);
    }
    // K tile [8][128]: fp16 gmem -> f32 smem
    {
        const __half* kp = g_K + (size_t)b*MM*NN + n0;
        int m = tid >> 5, p8 = (tid & 31)*4;
        half2 k01 = *(const half2*)(kp + (size_t)m*NN + p8);
        half2 k23 = *(const half2*)(kp + (size_t)m*NN + p8 + 2);
        float2 f01 = __half22float2(k01), f23 = __half22float2(k23);
        float* kr = s_K + m*TPX + p8;
        kr[0]=f01.x; kr[1]=f01.y; kr[2]=f23.x; kr[3]=f23.y;
    }
    if (tid < 64){
        float sc=fc2_bn[0*CC+tid], bi=fc2_bn[1*CC+tid];
        float mn=fc2_bn[2*CC+tid], vr=fc2_bn[3*CC+tid];
        float inv = sc*rsqrtf(vr+1e-5f);
        s_inv[tid]=inv; s_beta[tid]=bi-mn*inv;
    }
    __syncthreads();

    int w = tid >> 5, lane = tid & 31;
    int mt = w & 3, ph = w >> 2;
    int m0 = mt*16, p0 = ph*64;

    float acc[8][4];
    #pragma unroll
    for (int i=0;i<8;i++){ acc[i][0]=acc[i][1]=acc[i][2]=acc[i][3]=0.f; }

    int arow = m0 + (lane & 15), acol8 = (lane>>4)*8;
    int brow = (lane & 7) + 8*((lane>>3)&1), bcol8 = (lane>>4)*8;

    #pragma unroll
    for (int kt=0; kt<4; kt++){
        int k0 = kt*16;
        uint32_t a[4];
        ldsm4(a, sb + C_AH + (uint32_t)(arow*WS + k0 + acol8)*2);
        #pragma unroll
        for (int np=0; np<4; np++){
            uint32_t bF[4];
            ldsm4t(bF, sb + C_XH + (uint32_t)((k0+brow)*XS + p0 + np*16 + bcol8)*2);
            mma16816h(acc[2*np],   a, bF);
            mma16816h(acc[2*np+1], a, bF+2);
        }
    }

    __syncthreads();   // everyone done reading xH -> reuse as v_s

    // epilogue: xc = relu6(bn(D)) -> smem directly
    int g = lane >> 2, t2 = (lane & 3)*2;
    int o0 = m0 + g, o1 = o0 + 8;
    float i0 = s_inv[o0], e0 = s_beta[o0], i1 = s_inv[o1], e1 = s_beta[o1];
    #pragma unroll
    for (int nt=0; nt<8; nt++){
        int px = p0 + nt*8 + t2;
        v_s[ px   *65 + o0] = relu6f(acc[nt][0]*i0+e0);
        v_s[(px+1)*65 + o0] = relu6f(acc[nt][1]*i0+e0);
        v_s[ px   *65 + o1] = relu6f(acc[nt][2]*i1+e1);
        v_s[(px+1)*65 + o1] = relu6f(acc[nt][3]*i1+e1);
    }
    __syncthreads();

    // KV reduction over xc (split chains)
    {
        int m = tid >> 6, c = tid & 63;
        const float* k0r = s_K + m*TPX;
        const float* k1r = s_K + (m+4)*TPX;
        float a0=0.f, a1=0.f, c0=0.f, c1=0.f;
        #pragma unroll 8
        for (int p=0;p<TPX/2;p++){
            float v = v_s[p*65 + c];
            a0 = fmaf(k0r[p], v, a0);
            a1 = fmaf(k1r[p], v, a1);
        }
        #pragma unroll 8
        for (int p=TPX/2;p<TPX;p++){
            float v = v_s[p*65 + c];
            c0 = fmaf(k0r[p], v, c0);
            c1 = fmaf(k1r[p], v, c1);
        }
        atomicAdd(&g_KV[b*MM*CC + m*CC     + c], a0+c0);
        atomicAdd(&g_KV[b*MM*CC + (m+4)*CC + c], a1+c1);
    }
}

// ---------------------------------------------------------------------------
// K5: out = x + gamma * (Qt . KV) * norm.
// 2 px/thread (float2), 2-way channel split; Q read as fp16.
// ---------------------------------------------------------------------------
__global__ __launch_bounds__(256) void k_out(
    const float* __restrict__ x, const float* __restrict__ gamma,
    float* __restrict__ out)
{
    __shared__ __align__(16) float s_kv[MM*32];
    __shared__ float s_ks[MM];
    int tid = threadIdx.x;
    int p2 = (blockIdx.x*256 + tid)*2;
    int b = p2/NN, n = p2%NN;     // 512 | NN -> b block-uniform
    int co = blockIdx.y*32;

    if (tid < MM*32){
        int m = tid>>5, j = tid&31;
        s_kv[tid] = g_KV[b*MM*CC + m*CC + co + j];
    }
    if (tid<MM) s_ks[tid] = g_Ksum[b*MM+tid] + 1e-6f;
    __syncthreads();

    float2 q[MM];
    #pragma unroll
    for (int m=0;m<MM;m++){
        half2 qh = *(const half2*)(g_Q + (size_t)b*MM*NN + (size_t)m*NN + n);
        q[m] = __half22float2(qh);
    }

    float dx=0.f, dy=0.f;
    #pragma unroll
    for (int m=0;m<MM;m++){
        float ks = s_ks[m];
        dx = fmaf(q[m].x, ks, dx);
        dy = fmaf(q[m].y, ks, dy);
    }
    float gm = gamma[0];
    float gsx = gm/dx, gsy = gm/dy;

    const float* xb = x + (size_t)b*CC*NN + (size_t)co*NN + n;
    float* ob = out + (size_t)b*CC*NN + (size_t)co*NN + n;

    #pragma unroll 8
    for (int c=0;c<32;c++){
        float ax=0.f, ay=0.f;
        #pragma unroll
        for (int m=0;m<MM;m++){
            float wv = s_kv[m*32 + c];
            ax = fmaf(q[m].x, wv, ax);
            ay = fmaf(q[m].y, wv, ay);
        }
        float2 xv = *(const float2*)(xb + (size_t)c*NN);
        xv.x = fmaf(gsx, ax, xv.x);
        xv.y = fmaf(gsy, ay, xv.y);
        *(float2*)(ob + (size_t)c*NN) = xv;
    }
}

// ---------------------------------------------------------------------------
extern "C" void kernel_launch(void* const* d_in, const int* in_sizes, int n_in,
                              void* d_out, int out_size)
{
    const float* x      = (const float*)d_in[0];
    const float* gamma  = (const float*)d_in[1];
    const float* q_w    = (const float*)d_in[2];
    const float* q_b    = (const float*)d_in[3];
    const float* k_w    = (const float*)d_in[4];
    const float* k_b    = (const float*)d_in[5];
    const float* v_w    = (const float*)d_in[6];
    const float* v_b    = (const float*)d_in[7];
    const float* fc1_w  = (const float*)d_in[8];
    const float* fc1_bn = (const float*)d_in[9];
    const float* c1_w   = (const float*)d_in[10];
    const float* c1_bn  = (const float*)d_in[11];
    const float* c2_w   = (const float*)d_in[12];
    const float* c2_bn  = (const float*)d_in[13];
    const float* fc2_w  = (const float*)d_in[14];
    const float* fc2_bn = (const float*)d_in[15];
    float* out = (float*)d_out;

    cudaFuncSetAttribute(k_front,  cudaFuncAttributeMaxDynamicSharedMemorySize, F_SMEM);
    cudaFuncSetAttribute(k_fc2kv,  cudaFuncAttributeMaxDynamicSharedMemorySize, C_SMEM);

    k_zero<<<8,256>>>();
    k_front<<<dim3(NN/TPX,BB),288,F_SMEM>>>(x,q_w,q_b,k_w,k_b,v_w,v_b,fc1_w,fc1_bn);
    k_dw<<<dim3(WW/32,HH/16,BB*CC),dim3(16,16)>>>(c1_w,c1_bn,c2_w,c2_bn);
    k_fc2kv<<<dim3(NN/TPX,BB),256,C_SMEM>>>(fc2_w,fc2_bn);
    k_out<<<dim3(BN/512,2),256>>>(x,gamma,out);
}

// round 16
// speedup vs baseline: 1.2500x; 1.1550x over previous
#include <cuda_runtime.h>
#include <cuda_fp16.h>
#include <math.h>
#include <stdint.h>

#define BB 4
#define CC 64
#define MM 8
#define HH 224
#define WW 224
#define NN (HH*WW)      // 50176
#define BN (BB*NN)      // 200704
#define TPX 128         // pixels per CTA tile

// Scratch (static device globals — allocation-free per harness rules)
__device__ __half g_h[BB*CC*NN];
__device__ __half g_s[BB*CC*NN];
__device__ __half g_Q[BB*MM*NN];
__device__ __half g_K[BB*MM*NN];
__device__ float g_KV[BB*MM*CC];
__device__ float g_Ksum[BB*MM];
__device__ __half g_wF[144*64];   // pre-converted front weights [v|fc1|q|k]
__device__ __half g_wC[64*64];    // pre-converted fc2 weights

__device__ __forceinline__ float relu6f(float x){ return fminf(fmaxf(x,0.f),6.f); }
__device__ __forceinline__ float softplusf(float x){
    return fmaxf(x,0.f) + __logf(1.f + __expf(-fabsf(x)));
}
__device__ __forceinline__ uint32_t smem_u32(const void* p){
    uint32_t a;
    asm("{ .reg .u64 t; cvta.to.shared.u64 t, %1; cvt.u32.u64 %0, t; }" : "=r"(a) : "l"(p));
    return a;
}
__device__ __forceinline__ uint32_t packh2(float a, float b){
    half2 h = __floats2half2_rn(a, b);
    return *(uint32_t*)&h;
}
__device__ __forceinline__ void ldsm4(uint32_t* r, uint32_t a){
    asm volatile("ldmatrix.sync.aligned.m8n8.x4.shared.b16 {%0,%1,%2,%3}, [%4];"
        : "=r"(r[0]),"=r"(r[1]),"=r"(r[2]),"=r"(r[3]) : "r"(a));
}
__device__ __forceinline__ void ldsm4t(uint32_t* r, uint32_t a){
    asm volatile("ldmatrix.sync.aligned.m8n8.x4.trans.shared.b16 {%0,%1,%2,%3}, [%4];"
        : "=r"(r[0]),"=r"(r[1]),"=r"(r[2]),"=r"(r[3]) : "r"(a));
}
__device__ __forceinline__ void mma16816h(float* d, const uint32_t* a, const uint32_t* b){
    asm volatile("mma.sync.aligned.m16n8k16.row.col.f32.f16.f16.f32 "
        "{%0,%1,%2,%3}, {%4,%5,%6,%7}, {%8,%9}, {%0,%1,%2,%3};"
        : "+f"(d[0]),"+f"(d[1]),"+f"(d[2]),"+f"(d[3])
        : "r"(a[0]),"r"(a[1]),"r"(a[2]),"r"(a[3]), "r"(b[0]),"r"(b[1]));
}

// zero accumulators + pre-convert weights to fp16
__global__ void k_prep(
    const float* __restrict__ q_w, const float* __restrict__ k_w,
    const float* __restrict__ v_w, const float* __restrict__ fc1_w,
    const float* __restrict__ fc2_w)
{
    int t = blockIdx.x*blockDim.x + threadIdx.x;   // 16*256 = 4096 threads
    if (t < BB*MM*CC) g_KV[t]   = 0.f;
    if (t < BB*MM)    g_Ksum[t] = 0.f;
    for (int i=t; i<144*64; i+=4096){
        int o = i>>6, c = i&63;
        float v = (o<64) ? v_w[o*64+c]
                : (o<128)? fc1_w[(o-64)*64+c]
                : (o<136)? q_w[(o-128)*64+c]
                :          k_w[(o-136)*64+c];
        g_wF[i] = __float2half(v);
    }
    if (t < 4096) g_wC[t] = __float2half(fc2_w[t]);
}

// ---------------------------------------------------------------------------
// K1 front (fp16 mma.sync): D[144 out, 128 px] = W[144,64] x Xt[64,128]
// outputs: [v(0..63) | fc1(64..127) | q(128..135) | k(136..143)]
// 288 threads = 9 warps. KV-partial via 2nd MMA on V fragments (K staged f16).
// ---------------------------------------------------------------------------
#define F_WH  0
#define F_XH  20736
#define F_KS  20736     // alias of XH after mainloop: [16][136] f16 (rows 8-15 zero)
#define F_CST 38144
#define F_SMEM 38976
#define WS 72     // weight smem row stride (f16 elems)
#define XS 136    // x smem row stride (f16 elems)
#define KS 136    // K_s row stride (f16 elems)

__global__ __launch_bounds__(288,2) void k_front(
    const float* __restrict__ x,
    const float* __restrict__ q_b, const float* __restrict__ k_b,
    const float* __restrict__ v_b, const float* __restrict__ fc1_bn)
{
    extern __shared__ char sm[];
    __half* wH = (__half*)(sm + F_WH);
    __half* xH = (__half*)(sm + F_XH);
    __half* K_s = (__half*)(sm + F_KS);
    float* s_vb   = (float*)(sm + F_CST);         // 64
    float* s_finv = s_vb + 64;                    // 64
    float* s_fbeta= s_finv + 64;                  // 64
    float* s_qb   = s_fbeta + 64;                 // 8
    float* s_kb   = s_qb + 8;                     // 8
    uint32_t sb = smem_u32(sm);

    int tid = threadIdx.x;
    int b  = blockIdx.y;
    int n0 = blockIdx.x * TPX;

    // weights: raw fp16 copy (pre-converted by k_prep)
    for (int i=tid; i<144*8; i+=288){
        int o = i>>3, c8 = (i&7)<<3;
        *(uint4*)(wH + o*WS + c8) = *(const uint4*)(g_wF + o*64 + c8);
    }
    // x tile: [64 ch][128 px] -> fp16, float4 loads
    const float* xb = x + (size_t)b*CC*NN + n0;
    for (int i=tid; i<64*32; i+=288){
        int c = i>>5, p4 = (i&31)<<2;
        float4 v = *(const float4*)(xb + (size_t)c*NN + p4);
        uint2 h;
        h.x = packh2(v.x, v.y);
        h.y = packh2(v.z, v.w);
        *(uint2*)(xH + c*XS + p4) = h;
    }
    if (tid < 64){
        s_vb[tid] = v_b[tid];
        float sc=fc1_bn[0*CC+tid], bi=fc1_bn[1*CC+tid];
        float mn=fc1_bn[2*CC+tid], vr=fc1_bn[3*CC+tid];
        float inv = sc*rsqrtf(vr+1e-5f);
        s_finv[tid]=inv; s_fbeta[tid]=bi-mn*inv;
    } else if (tid < 72){
        s_qb[tid-64] = q_b[tid-64];
        s_kb[tid-64] = k_b[tid-64];
    }
    __syncthreads();

    int w = tid >> 5, lane = tid & 31;
    int m0 = w*16;

    float acc[16][4];
    #pragma unroll
    for (int i=0;i<16;i++){ acc[i][0]=acc[i][1]=acc[i][2]=acc[i][3]=0.f; }

    int arow = m0 + (lane & 15), acol8 = (lane>>4)*8;
    int brow = (lane & 7) + 8*((lane>>3)&1), bcol8 = (lane>>4)*8;

    #pragma unroll
    for (int kt=0; kt<4; kt++){
        int k0 = kt*16;
        uint32_t a[4];
        ldsm4(a, sb + F_WH + (uint32_t)(arow*WS + k0 + acol8)*2);
        #pragma unroll
        for (int np=0; np<8; np++){
            uint32_t bF[4];
            ldsm4t(bF, sb + F_XH + (uint32_t)((k0+brow)*XS + np*16 + bcol8)*2);
            mma16816h(acc[2*np],   a, bF);
            mma16816h(acc[2*np+1], a, bF+2);
        }
    }

    __syncthreads();   // sync1: mainloop smem reads done -> K_s alias safe

    int g = lane >> 2, t2 = (lane & 3)*2;
    if (w < 4){
        // zero pad K_s rows 8..15 (2 rows per warp)
        int r0 = 8 + 2*w;
        for (int j=lane; j<KS; j+=32){
            K_s[r0*KS + j]     = __ushort_as_half(0);
            K_s[(r0+1)*KS + j] = __ushort_as_half(0);
        }
    } else if (w < 8){
        int o0 = m0 - 64 + g, o1 = o0 + 8;
        float i0=s_finv[o0], e0=s_fbeta[o0], i1=s_finv[o1], e1=s_fbeta[o1];
        __half* p0 = g_h + ((size_t)b*CC + o0)*NN + n0 + t2;
        __half* p1 = g_h + ((size_t)b*CC + o1)*NN + n0 + t2;
        #pragma unroll
        for (int nt=0; nt<16; nt++){
            *(half2*)(p0 + nt*8) = __floats2half2_rn(relu6f(acc[nt][0]*i0+e0), relu6f(acc[nt][1]*i0+e0));
            *(half2*)(p1 + nt*8) = __floats2half2_rn(relu6f(acc[nt][2]*i1+e1), relu6f(acc[nt][3]*i1+e1));
        }
    } else {
        // rows g -> Q[m=g], rows g+8 -> K[m=g]
        float bq = s_qb[g], bk = s_kb[g];
        __half* pq = g_Q + ((size_t)b*MM + g)*NN + n0 + t2;
        __half* pk = g_K + ((size_t)b*MM + g)*NN + n0 + t2;
        float ksum = 0.f;
        #pragma unroll
        for (int nt=0; nt<16; nt++){
            int px = nt*8 + t2;
            float q0 = softplusf(acc[nt][0]+bq), q1 = softplusf(acc[nt][1]+bq);
            float k0v = softplusf(acc[nt][2]+bk), k1v = softplusf(acc[nt][3]+bk);
            *(half2*)(pq + nt*8) = __floats2half2_rn(q0, q1);
            half2 kk = __floats2half2_rn(k0v, k1v);
            *(half2*)(pk + nt*8) = kk;
            *(half2*)(K_s + g*KS + px) = kk;
            ksum += k0v + k1v;
        }
        ksum += __shfl_xor_sync(0xffffffffu, ksum, 1);
        ksum += __shfl_xor_sync(0xffffffffu, ksum, 2);
        if ((lane & 3) == 0) atomicAdd(&g_Ksum[b*MM + g], ksum);
    }
    __syncthreads();   // sync2: K_s ready

    // GEMM2: KV[m, ch] += sum_px K[m,px] * (Vconv[ch,px]+vb[ch])  (warps 0..3)
    if (w < 4){
        float vb0 = s_vb[m0+g], vb1 = s_vb[m0+8+g];
        float d2lo[4] = {0.f,0.f,0.f,0.f}, d2hi[4] = {0.f,0.f,0.f,0.f};
        #pragma unroll
        for (int np=0; np<8; np++){
            uint32_t aK[4];
            ldsm4(aK, sb + F_KS + (uint32_t)((lane&15)*KS + np*16 + (lane>>4)*8)*2);
            uint32_t bl[2], bh[2];
            bl[0] = packh2(acc[2*np][0]+vb0,   acc[2*np][1]+vb0);
            bl[1] = packh2(acc[2*np+1][0]+vb0, acc[2*np+1][1]+vb0);
            bh[0] = packh2(acc[2*np][2]+vb1,   acc[2*np][3]+vb1);
            bh[1] = packh2(acc[2*np+1][2]+vb1, acc[2*np+1][3]+vb1);
            mma16816h(d2lo, aK, bl);
            mma16816h(d2hi, aK, bh);
        }
        float* kvb = g_KV + b*MM*CC + g*CC;
        atomicAdd(kvb + m0 + t2,       d2lo[0]);
        atomicAdd(kvb + m0 + t2 + 1,   d2lo[1]);
        atomicAdd(kvb + m0+8 + t2,     d2hi[0]);
        atomicAdd(kvb + m0+8 + t2 + 1, d2hi[1]);
    }
}

// ---------------------------------------------------------------------------
// K2: depthwise 5x5 + 3x3 (both BN+ReLU6), summed -> g_s (fp16 in/out)
// HFMA2: 2 horizontal px per thread packed in half2. 3x3 reuses 5x5 pairs.
// ---------------------------------------------------------------------------
__global__ __launch_bounds__(256) void k_dw(
    const float* __restrict__ w5, const float* __restrict__ bn5,
    const float* __restrict__ w3, const float* __restrict__ bn3)
{
    int bc = blockIdx.z;
    int c  = bc & (CC-1);
    int y0 = blockIdx.y*16, x0 = blockIdx.x*32;

    __shared__ __half t[20][40];
    __shared__ __half2 s_w5[25], s_w3[9];
    __shared__ float s_c[4];

    int tid = threadIdx.y*16 + threadIdx.x;
    const __half* plane = g_h + (size_t)bc*NN;

    for (int i=tid;i<20*36;i+=256){
        int ly=i/36, lx=i%36;
        int gy=y0+ly-2, gx=x0+lx-2;
        __half v = __ushort_as_half(0);
        if (gy>=0 && gy<HH && gx>=0 && gx<WW) v = plane[gy*WW+gx];
        t[ly][lx] = v;
    }
    if (tid < 25)               s_w5[tid]    = __float2half2_rn(w5[c*25+tid]);
    if (tid >= 32 && tid < 41)  s_w3[tid-32] = __float2half2_rn(w3[c*9+tid-32]);
    if (tid == 64){
        float inv = bn5[0*CC+c]*rsqrtf(bn5[3*CC+c]+1e-5f);
        s_c[0]=inv; s_c[1]=bn5[1*CC+c]-bn5[2*CC+c]*inv;
    }
    if (tid == 80){
        float inv = bn3[0*CC+c]*rsqrtf(bn3[3*CC+c]+1e-5f);
        s_c[2]=inv; s_c[3]=bn3[1*CC+c]-bn3[2*CC+c]*inv;
    }
    __syncthreads();

    int ty = threadIdx.y;        // 0..15 (row)
    int tx2 = threadIdx.x*2;     // 0,2,..,30 (2 px per thread)

    __half2 acc5 = __float2half2_rn(0.f);
    __half2 acc3 = __float2half2_rn(0.f);
    #pragma unroll
    for (int i=0;i<5;i++){
        const __half2* r = (const __half2*)&t[ty+i][tx2];   // tx2 even -> 4B aligned
        __half2 A = r[0], B = r[1], C = r[2];               // cols {0,1},{2,3},{4,5}
        __half2 p1 = __halves2half2(__high2half(A), __low2half(B));  // {1,2}
        __half2 p3 = __halves2half2(__high2half(B), __low2half(C));  // {3,4}
        acc5 = __hfma2(A,  s_w5[i*5+0], acc5);
        acc5 = __hfma2(p1, s_w5[i*5+1], acc5);
        acc5 = __hfma2(B,  s_w5[i*5+2], acc5);
        acc5 = __hfma2(p3, s_w5[i*5+3], acc5);
        acc5 = __hfma2(C,  s_w5[i*5+4], acc5);
        if (i >= 1 && i <= 3){
            int j = i-1;
            acc3 = __hfma2(p1, s_w3[j*3+0], acc3);
            acc3 = __hfma2(B,  s_w3[j*3+1], acc3);
            acc3 = __hfma2(p3, s_w3[j*3+2], acc3);
        }
    }

    float2 a5 = __half22float2(acc5);
    float2 a3 = __half22float2(acc3);
    float ra = relu6f(a5.x*s_c[0]+s_c[1]) + relu6f(a3.x*s_c[2]+s_c[3]);
    float rb = relu6f(a5.y*s_c[0]+s_c[1]) + relu6f(a3.y*s_c[2]+s_c[3]);
    *(half2*)(g_s + (size_t)bc*NN + (y0+ty)*WW + (x0+tx2)) = __floats2half2_rn(ra, rb);
}

// ---------------------------------------------------------------------------
// K3: fc2 (fp16 mma.sync) + fused KV of xc via smem reduce.
// ---------------------------------------------------------------------------
#define C_AH  0
#define C_XH  9216
#define C_VS  0
#define C_KT  33280
#define C_INV 37376
#define C_BETA 37632
#define C_SMEM 37888

__global__ __launch_bounds__(256,4) void k_fc2kv(
    const float* __restrict__ fc2_bn)
{
    extern __shared__ char sm[];
    __half* aH = (__half*)(sm + C_AH);
    __half* xH = (__half*)(sm + C_XH);
    float* s_K   = (float*)(sm + C_KT);
    float* s_inv = (float*)(sm + C_INV);
    float* s_beta= (float*)(sm + C_BETA);
    float* v_s   = (float*)(sm + C_VS);   // alias, used after mainloop
    uint32_t sb = smem_u32(sm);

    int tid = threadIdx.x;
    int b  = blockIdx.y;
    int n0 = blockIdx.x * TPX;

    // weights: raw fp16 copy (pre-converted)
    for (int i=tid; i<64*8; i+=256){
        int o = i>>3, c8 = (i&7)<<3;
        *(uint4*)(aH + o*WS + c8) = *(const uint4*)(g_wC + o*64 + c8);
    }
    // s tile [64 ch][128 px] — raw fp16 copy
    const __half* sp = g_s + (size_t)b*CC*NN + n0;
    for (int i=tid; i<64*16; i+=256){
        int c = i>>4, p8 = (i&15)<<3;
        *(uint4*)(xH + c*XS + p8) = *(const uint4*)(sp + (size_t)c*NN + p8);
    }
    // K tile [8][128]: fp16 gmem -> f32 smem
    {
        const __half* kp = g_K + (size_t)b*MM*NN + n0;
        int m = tid >> 5, p8 = (tid & 31)*4;
        half2 k01 = *(const half2*)(kp + (size_t)m*NN + p8);
        half2 k23 = *(const half2*)(kp + (size_t)m*NN + p8 + 2);
        float2 f01 = __half22float2(k01), f23 = __half22float2(k23);
        float* kr = s_K + m*TPX + p8;
        kr[0]=f01.x; kr[1]=f01.y; kr[2]=f23.x; kr[3]=f23.y;
    }
    if (tid < 64){
        float sc=fc2_bn[0*CC+tid], bi=fc2_bn[1*CC+tid];
        float mn=fc2_bn[2*CC+tid], vr=fc2_bn[3*CC+tid];
        float inv = sc*rsqrtf(vr+1e-5f);
        s_inv[tid]=inv; s_beta[tid]=bi-mn*inv;
    }
    __syncthreads();

    int w = tid >> 5, lane = tid & 31;
    int mt = w & 3, ph = w >> 2;
    int m0 = mt*16, p0 = ph*64;

    float acc[8][4];
    #pragma unroll
    for (int i=0;i<8;i++){ acc[i][0]=acc[i][1]=acc[i][2]=acc[i][3]=0.f; }

    int arow = m0 + (lane & 15), acol8 = (lane>>4)*8;
    int brow = (lane & 7) + 8*((lane>>3)&1), bcol8 = (lane>>4)*8;

    #pragma unroll
    for (int kt=0; kt<4; kt++){
        int k0 = kt*16;
        uint32_t a[4];
        ldsm4(a, sb + C_AH + (uint32_t)(arow*WS + k0 + acol8)*2);
        #pragma unroll
        for (int np=0; np<4; np++){
            uint32_t bF[4];
            ldsm4t(bF, sb + C_XH + (uint32_t)((k0+brow)*XS + p0 + np*16 + bcol8)*2);
            mma16816h(acc[2*np],   a, bF);
            mma16816h(acc[2*np+1], a, bF+2);
        }
    }

    __syncthreads();   // everyone done reading xH -> reuse as v_s

    // epilogue: xc = relu6(bn(D)) -> smem directly
    int g = lane >> 2, t2 = (lane & 3)*2;
    int o0 = m0 + g, o1 = o0 + 8;
    float i0 = s_inv[o0], e0 = s_beta[o0], i1 = s_inv[o1], e1 = s_beta[o1];
    #pragma unroll
    for (int nt=0; nt<8; nt++){
        int px = p0 + nt*8 + t2;
        v_s[ px   *65 + o0] = relu6f(acc[nt][0]*i0+e0);
        v_s[(px+1)*65 + o0] = relu6f(acc[nt][1]*i0+e0);
        v_s[ px   *65 + o1] = relu6f(acc[nt][2]*i1+e1);
        v_s[(px+1)*65 + o1] = relu6f(acc[nt][3]*i1+e1);
    }
    __syncthreads();

    // KV reduction over xc (split chains)
    {
        int m = tid >> 6, c = tid & 63;
        const float* k0r = s_K + m*TPX;
        const float* k1r = s_K + (m+4)*TPX;
        float a0=0.f, a1=0.f, c0=0.f, c1=0.f;
        #pragma unroll 8
        for (int p=0;p<TPX/2;p++){
            float v = v_s[p*65 + c];
            a0 = fmaf(k0r[p], v, a0);
            a1 = fmaf(k1r[p], v, a1);
        }
        #pragma unroll 8
        for (int p=TPX/2;p<TPX;p++){
            float v = v_s[p*65 + c];
            c0 = fmaf(k0r[p], v, c0);
            c1 = fmaf(k1r[p], v, c1);
        }
        atomicAdd(&g_KV[b*MM*CC + m*CC     + c], a0+c0);
        atomicAdd(&g_KV[b*MM*CC + (m+4)*CC + c], a1+c1);
    }
}

// ---------------------------------------------------------------------------
// K5: out = x + gamma * (Qt . KV) * norm.
// 4 px/thread (float4), 4-way channel split (16 ch each); Q read fp16.
// ---------------------------------------------------------------------------
__global__ __launch_bounds__(256) void k_out(
    const float* __restrict__ x, const float* __restrict__ gamma,
    float* __restrict__ out)
{
    __shared__ __align__(16) float s_kv[MM*16];
    __shared__ float s_ks[MM];
    int tid = threadIdx.x;
    int p4 = (blockIdx.x*256 + tid)*4;
    int b = p4/NN, n = p4%NN;     // 1024 | NN -> b block-uniform
    int co = blockIdx.y*16;

    if (tid < MM*16){
        int m = tid>>4, j = tid&15;
        s_kv[tid] = g_KV[b*MM*CC + m*CC + co + j];
    }
    if (tid<MM) s_ks[tid] = g_Ksum[b*MM+tid] + 1e-6f;
    __syncthreads();

    float4 q[MM];
    #pragma unroll
    for (int m=0;m<MM;m++){
        uint2 qr = *(const uint2*)(g_Q + (size_t)b*MM*NN + (size_t)m*NN + n);
        float2 q01 = __half22float2(*(half2*)&qr.x);
        float2 q23 = __half22float2(*(half2*)&qr.y);
        q[m] = make_float4(q01.x, q01.y, q23.x, q23.y);
    }

    float4 den = make_float4(0.f,0.f,0.f,0.f);
    #pragma unroll
    for (int m=0;m<MM;m++){
        float ks = s_ks[m];
        den.x = fmaf(q[m].x, ks, den.x); den.y = fmaf(q[m].y, ks, den.y);
        den.z = fmaf(q[m].z, ks, den.z); den.w = fmaf(q[m].w, ks, den.w);
    }
    float gm = gamma[0];
    float4 gs = make_float4(gm/den.x, gm/den.y, gm/den.z, gm/den.w);

    const float* xb = x + (size_t)b*CC*NN + (size_t)co*NN + n;
    float* ob = out + (size_t)b*CC*NN + (size_t)co*NN + n;

    #pragma unroll 4
    for (int c=0;c<16;c++){
        float ax=0.f, ay=0.f, az=0.f, aw=0.f;
        #pragma unroll
        for (int m=0;m<MM;m++){
            float wv = s_kv[m*16 + c];
            ax = fmaf(q[m].x, wv, ax); ay = fmaf(q[m].y, wv, ay);
            az = fmaf(q[m].z, wv, az); aw = fmaf(q[m].w, wv, aw);
        }
        float4 xv = *(const float4*)(xb + (size_t)c*NN);
        xv.x = fmaf(gs.x, ax, xv.x); xv.y = fmaf(gs.y, ay, xv.y);
        xv.z = fmaf(gs.z, az, xv.z); xv.w = fmaf(gs.w, aw, xv.w);
        *(float4*)(ob + (size_t)c*NN) = xv;
    }
}

// ---------------------------------------------------------------------------
extern "C" void kernel_launch(void* const* d_in, const int* in_sizes, int n_in,
                              void* d_out, int out_size)
{
    const float* x      = (const float*)d_in[0];
    const float* gamma  = (const float*)d_in[1];
    const float* q_w    = (const float*)d_in[2];
    const float* q_b    = (const float*)d_in[3];
    const float* k_w    = (const float*)d_in[4];
    const float* k_b    = (const float*)d_in[5];
    const float* v_w    = (const float*)d_in[6];
    const float* v_b    = (const float*)d_in[7];
    const float* fc1_w  = (const float*)d_in[8];
    const float* fc1_bn = (const float*)d_in[9];
    const float* c1_w   = (const float*)d_in[10];
    const float* c1_bn  = (const float*)d_in[11];
    const float* c2_w   = (const float*)d_in[12];
    const float* c2_bn  = (const float*)d_in[13];
    const float* fc2_w  = (const float*)d_in[14];
    const float* fc2_bn = (const float*)d_in[15];
    float* out = (float*)d_out;

    cudaFuncSetAttribute(k_front,  cudaFuncAttributeMaxDynamicSharedMemorySize, F_SMEM);
    cudaFuncSetAttribute(k_fc2kv,  cudaFuncAttributeMaxDynamicSharedMemorySize, C_SMEM);

    k_prep<<<16,256>>>(q_w,k_w,v_w,fc1_w,fc2_w);
    k_front<<<dim3(NN/TPX,BB),288,F_SMEM>>>(x,q_b,k_b,v_b,fc1_bn);
    k_dw<<<dim3(WW/32,HH/16,BB*CC),dim3(16,16)>>>(c1_w,c1_bn,c2_w,c2_bn);
    k_fc2kv<<<dim3(NN/TPX,BB),256,C_SMEM>>>(fc2_bn);
    k_out<<<dim3(BN/1024,4),256>>>(x,gamma,out);
}

// round 17
// speedup vs baseline: 1.2705x; 1.0164x over previous
#include <cuda_runtime.h>
#include <cuda_fp16.h>
#include <math.h>
#include <stdint.h>

#define BB 4
#define CC 64
#define MM 8
#define HH 224
#define WW 224
#define NN (HH*WW)      // 50176
#define BN (BB*NN)      // 200704
#define TPX 128         // pixels per CTA tile

// Scratch (static device globals — allocation-free per harness rules)
__device__ __half g_h[BB*CC*NN];
__device__ __half g_s[BB*CC*NN];
__device__ __half g_Q[BB*MM*NN];
__device__ __half g_K[BB*MM*NN];
__device__ float g_KV[BB*MM*CC];
__device__ float g_Ksum[BB*MM];
__device__ __half g_wF[144*64];   // pre-converted front weights [v|fc1|q|k]
__device__ __half g_wC[64*64];    // pre-converted fc2 weights

__device__ __forceinline__ float relu6f(float x){ return fminf(fmaxf(x,0.f),6.f); }
__device__ __forceinline__ float softplusf(float x){
    return fmaxf(x,0.f) + __logf(1.f + __expf(-fabsf(x)));
}
__device__ __forceinline__ uint32_t smem_u32(const void* p){
    uint32_t a;
    asm("{ .reg .u64 t; cvta.to.shared.u64 t, %1; cvt.u32.u64 %0, t; }" : "=r"(a) : "l"(p));
    return a;
}
__device__ __forceinline__ uint32_t packh2(float a, float b){
    half2 h = __floats2half2_rn(a, b);
    return *(uint32_t*)&h;
}
__device__ __forceinline__ void ldsm4(uint32_t* r, uint32_t a){
    asm volatile("ldmatrix.sync.aligned.m8n8.x4.shared.b16 {%0,%1,%2,%3}, [%4];"
        : "=r"(r[0]),"=r"(r[1]),"=r"(r[2]),"=r"(r[3]) : "r"(a));
}
__device__ __forceinline__ void ldsm4t(uint32_t* r, uint32_t a){
    asm volatile("ldmatrix.sync.aligned.m8n8.x4.trans.shared.b16 {%0,%1,%2,%3}, [%4];"
        : "=r"(r[0]),"=r"(r[1]),"=r"(r[2]),"=r"(r[3]) : "r"(a));
}
__device__ __forceinline__ void mma16816h(float* d, const uint32_t* a, const uint32_t* b){
    asm volatile("mma.sync.aligned.m16n8k16.row.col.f32.f16.f16.f32 "
        "{%0,%1,%2,%3}, {%4,%5,%6,%7}, {%8,%9}, {%0,%1,%2,%3};"
        : "+f"(d[0]),"+f"(d[1]),"+f"(d[2]),"+f"(d[3])
        : "r"(a[0]),"r"(a[1]),"r"(a[2]),"r"(a[3]), "r"(b[0]),"r"(b[1]));
}

// zero accumulators + pre-convert weights to fp16
__global__ void k_prep(
    const float* __restrict__ q_w, const float* __restrict__ k_w,
    const float* __restrict__ v_w, const float* __restrict__ fc1_w,
    const float* __restrict__ fc2_w)
{
    int t = blockIdx.x*blockDim.x + threadIdx.x;   // 16*256 = 4096 threads
    if (t < BB*MM*CC) g_KV[t]   = 0.f;
    if (t < BB*MM)    g_Ksum[t] = 0.f;
    for (int i=t; i<144*64; i+=4096){
        int o = i>>6, c = i&63;
        float v = (o<64) ? v_w[o*64+c]
                : (o<128)? fc1_w[(o-64)*64+c]
                : (o<136)? q_w[(o-128)*64+c]
                :          k_w[(o-136)*64+c];
        g_wF[i] = __float2half(v);
    }
    if (t < 4096) g_wC[t] = __float2half(fc2_w[t]);
}

// ---------------------------------------------------------------------------
// K1 front (fp16 mma.sync): D[144 out, 128 px] = W[144,64] x Xt[64,128]
// outputs: [v(0..63) | fc1(64..127) | q(128..135) | k(136..143)]
// 288 threads = 9 warps. KV-partial via 2nd MMA on V fragments (K staged f16).
// ---------------------------------------------------------------------------
#define F_WH  0
#define F_XH  20736
#define F_KS  20736     // alias of XH after mainloop: [16][136] f16 (rows 8-15 zero)
#define F_CST 38144
#define F_SMEM 38976
#define WS 72     // weight smem row stride (f16 elems)
#define XS 136    // x smem row stride (f16 elems)
#define KS 136    // K_s row stride (f16 elems)

__global__ __launch_bounds__(288,2) void k_front(
    const float* __restrict__ x,
    const float* __restrict__ q_b, const float* __restrict__ k_b,
    const float* __restrict__ v_b, const float* __restrict__ fc1_bn)
{
    extern __shared__ char sm[];
    __half* wH = (__half*)(sm + F_WH);
    __half* xH = (__half*)(sm + F_XH);
    __half* K_s = (__half*)(sm + F_KS);
    float* s_vb   = (float*)(sm + F_CST);         // 64
    float* s_finv = s_vb + 64;                    // 64
    float* s_fbeta= s_finv + 64;                  // 64
    float* s_qb   = s_fbeta + 64;                 // 8
    float* s_kb   = s_qb + 8;                     // 8
    uint32_t sb = smem_u32(sm);

    int tid = threadIdx.x;
    int b  = blockIdx.y;
    int n0 = blockIdx.x * TPX;

    // weights: raw fp16 copy (pre-converted by k_prep)
    for (int i=tid; i<144*8; i+=288){
        int o = i>>3, c8 = (i&7)<<3;
        *(uint4*)(wH + o*WS + c8) = *(const uint4*)(g_wF + o*64 + c8);
    }
    // x tile: [64 ch][128 px] -> fp16, float4 loads
    const float* xb = x + (size_t)b*CC*NN + n0;
    for (int i=tid; i<64*32; i+=288){
        int c = i>>5, p4 = (i&31)<<2;
        float4 v = *(const float4*)(xb + (size_t)c*NN + p4);
        uint2 h;
        h.x = packh2(v.x, v.y);
        h.y = packh2(v.z, v.w);
        *(uint2*)(xH + c*XS + p4) = h;
    }
    if (tid < 64){
        s_vb[tid] = v_b[tid];
        float sc=fc1_bn[0*CC+tid], bi=fc1_bn[1*CC+tid];
        float mn=fc1_bn[2*CC+tid], vr=fc1_bn[3*CC+tid];
        float inv = sc*rsqrtf(vr+1e-5f);
        s_finv[tid]=inv; s_fbeta[tid]=bi-mn*inv;
    } else if (tid < 72){
        s_qb[tid-64] = q_b[tid-64];
        s_kb[tid-64] = k_b[tid-64];
    }
    __syncthreads();

    int w = tid >> 5, lane = tid & 31;
    int m0 = w*16;

    float acc[16][4];
    #pragma unroll
    for (int i=0;i<16;i++){ acc[i][0]=acc[i][1]=acc[i][2]=acc[i][3]=0.f; }

    int arow = m0 + (lane & 15), acol8 = (lane>>4)*8;
    int brow = (lane & 7) + 8*((lane>>3)&1), bcol8 = (lane>>4)*8;

    #pragma unroll
    for (int kt=0; kt<4; kt++){
        int k0 = kt*16;
        uint32_t a[4];
        ldsm4(a, sb + F_WH + (uint32_t)(arow*WS + k0 + acol8)*2);
        #pragma unroll
        for (int np=0; np<8; np++){
            uint32_t bF[4];
            ldsm4t(bF, sb + F_XH + (uint32_t)((k0+brow)*XS + np*16 + bcol8)*2);
            mma16816h(acc[2*np],   a, bF);
            mma16816h(acc[2*np+1], a, bF+2);
        }
    }

    __syncthreads();   // sync1: mainloop smem reads done -> K_s alias safe

    int g = lane >> 2, t2 = (lane & 3)*2;
    if (w < 4){
        // zero pad K_s rows 8..15 (2 rows per warp)
        int r0 = 8 + 2*w;
        for (int j=lane; j<KS; j+=32){
            K_s[r0*KS + j]     = __ushort_as_half(0);
            K_s[(r0+1)*KS + j] = __ushort_as_half(0);
        }
    } else if (w < 8){
        int o0 = m0 - 64 + g, o1 = o0 + 8;
        float i0=s_finv[o0], e0=s_fbeta[o0], i1=s_finv[o1], e1=s_fbeta[o1];
        __half* p0 = g_h + ((size_t)b*CC + o0)*NN + n0 + t2;
        __half* p1 = g_h + ((size_t)b*CC + o1)*NN + n0 + t2;
        #pragma unroll
        for (int nt=0; nt<16; nt++){
            *(half2*)(p0 + nt*8) = __floats2half2_rn(relu6f(acc[nt][0]*i0+e0), relu6f(acc[nt][1]*i0+e0));
            *(half2*)(p1 + nt*8) = __floats2half2_rn(relu6f(acc[nt][2]*i1+e1), relu6f(acc[nt][3]*i1+e1));
        }
    } else {
        // rows g -> Q[m=g], rows g+8 -> K[m=g]
        float bq = s_qb[g], bk = s_kb[g];
        __half* pq = g_Q + ((size_t)b*MM + g)*NN + n0 + t2;
        __half* pk = g_K + ((size_t)b*MM + g)*NN + n0 + t2;
        float ksum = 0.f;
        #pragma unroll
        for (int nt=0; nt<16; nt++){
            int px = nt*8 + t2;
            float q0 = softplusf(acc[nt][0]+bq), q1 = softplusf(acc[nt][1]+bq);
            float k0v = softplusf(acc[nt][2]+bk), k1v = softplusf(acc[nt][3]+bk);
            *(half2*)(pq + nt*8) = __floats2half2_rn(q0, q1);
            half2 kk = __floats2half2_rn(k0v, k1v);
            *(half2*)(pk + nt*8) = kk;
            *(half2*)(K_s + g*KS + px) = kk;
            ksum += k0v + k1v;
        }
        ksum += __shfl_xor_sync(0xffffffffu, ksum, 1);
        ksum += __shfl_xor_sync(0xffffffffu, ksum, 2);
        if ((lane & 3) == 0) atomicAdd(&g_Ksum[b*MM + g], ksum);
    }
    __syncthreads();   // sync2: K_s ready

    // GEMM2: KV[m, ch] += sum_px K[m,px] * (Vconv[ch,px]+vb[ch])  (warps 0..3)
    if (w < 4){
        float vb0 = s_vb[m0+g], vb1 = s_vb[m0+8+g];
        float d2lo[4] = {0.f,0.f,0.f,0.f}, d2hi[4] = {0.f,0.f,0.f,0.f};
        #pragma unroll
        for (int np=0; np<8; np++){
            uint32_t aK[4];
            ldsm4(aK, sb + F_KS + (uint32_t)((lane&15)*KS + np*16 + (lane>>4)*8)*2);
            uint32_t bl[2], bh[2];
            bl[0] = packh2(acc[2*np][0]+vb0,   acc[2*np][1]+vb0);
            bl[1] = packh2(acc[2*np+1][0]+vb0, acc[2*np+1][1]+vb0);
            bh[0] = packh2(acc[2*np][2]+vb1,   acc[2*np][3]+vb1);
            bh[1] = packh2(acc[2*np+1][2]+vb1, acc[2*np+1][3]+vb1);
            mma16816h(d2lo, aK, bl);
            mma16816h(d2hi, aK, bh);
        }
        float* kvb = g_KV + b*MM*CC + g*CC;
        atomicAdd(kvb + m0 + t2,       d2lo[0]);
        atomicAdd(kvb + m0 + t2 + 1,   d2lo[1]);
        atomicAdd(kvb + m0+8 + t2,     d2hi[0]);
        atomicAdd(kvb + m0+8 + t2 + 1, d2hi[1]);
    }
}

// ---------------------------------------------------------------------------
// K2: depthwise 5x5 + 3x3 (both BN+ReLU6), summed -> g_s (fp16 in/out)
// HFMA2 compute; half2-vectorized tile loader (borders take scalar fallback).
// ---------------------------------------------------------------------------
__global__ __launch_bounds__(256) void k_dw(
    const float* __restrict__ w5, const float* __restrict__ bn5,
    const float* __restrict__ w3, const float* __restrict__ bn3)
{
    int bc = blockIdx.z;
    int c  = bc & (CC-1);
    int y0 = blockIdx.y*16, x0 = blockIdx.x*32;

    __shared__ __half t[20][40];
    __shared__ __half2 s_w5[25], s_w3[9];
    __shared__ float s_c[4];

    int tid = threadIdx.y*16 + threadIdx.x;
    const __half* plane = g_h + (size_t)bc*NN;

    // tile load: 20 rows x 18 half2 (36 cols), aligned half2 in the interior
    for (int i=tid; i<20*18; i+=256){
        int ly = i/18, u = i%18;
        int gy = y0+ly-2;
        int gx = x0 + 2*u - 2;       // even
        half2 v = __halves2half2(__ushort_as_half(0), __ushort_as_half(0));
        if (gy>=0 && gy<HH){
            if (gx>=0 && gx+1<WW){
                v = *(const half2*)(plane + gy*WW + gx);
            } else {
                __half a = (gx>=0   && gx<WW)   ? plane[gy*WW+gx]   : __ushort_as_half(0);
                __half bvv = (gx+1>=0 && gx+1<WW) ? plane[gy*WW+gx+1] : __ushort_as_half(0);
                v = __halves2half2(a, bvv);
            }
        }
        *(half2*)&t[ly][2*u] = v;
    }
    if (tid < 25)               s_w5[tid]    = __float2half2_rn(w5[c*25+tid]);
    if (tid >= 32 && tid < 41)  s_w3[tid-32] = __float2half2_rn(w3[c*9+tid-32]);
    if (tid == 64){
        float inv = bn5[0*CC+c]*rsqrtf(bn5[3*CC+c]+1e-5f);
        s_c[0]=inv; s_c[1]=bn5[1*CC+c]-bn5[2*CC+c]*inv;
    }
    if (tid == 80){
        float inv = bn3[0*CC+c]*rsqrtf(bn3[3*CC+c]+1e-5f);
        s_c[2]=inv; s_c[3]=bn3[1*CC+c]-bn3[2*CC+c]*inv;
    }
    __syncthreads();

    int ty = threadIdx.y;        // 0..15 (row)
    int tx2 = threadIdx.x*2;     // 0,2,..,30 (2 px per thread)

    __half2 acc5 = __float2half2_rn(0.f);
    __half2 acc3 = __float2half2_rn(0.f);
    #pragma unroll
    for (int i=0;i<5;i++){
        const __half2* r = (const __half2*)&t[ty+i][tx2];   // tx2 even -> 4B aligned
        __half2 A = r[0], B = r[1], C = r[2];               // cols {0,1},{2,3},{4,5}
        __half2 p1 = __halves2half2(__high2half(A), __low2half(B));  // {1,2}
        __half2 p3 = __halves2half2(__high2half(B), __low2half(C));  // {3,4}
        acc5 = __hfma2(A,  s_w5[i*5+0], acc5);
        acc5 = __hfma2(p1, s_w5[i*5+1], acc5);
        acc5 = __hfma2(B,  s_w5[i*5+2], acc5);
        acc5 = __hfma2(p3, s_w5[i*5+3], acc5);
        acc5 = __hfma2(C,  s_w5[i*5+4], acc5);
        if (i >= 1 && i <= 3){
            int j = i-1;
            acc3 = __hfma2(p1, s_w3[j*3+0], acc3);
            acc3 = __hfma2(B,  s_w3[j*3+1], acc3);
            acc3 = __hfma2(p3, s_w3[j*3+2], acc3);
        }
    }

    float2 a5 = __half22float2(acc5);
    float2 a3 = __half22float2(acc3);
    float ra = relu6f(a5.x*s_c[0]+s_c[1]) + relu6f(a3.x*s_c[2]+s_c[3]);
    float rb = relu6f(a5.y*s_c[0]+s_c[1]) + relu6f(a3.y*s_c[2]+s_c[3]);
    *(half2*)(g_s + (size_t)bc*NN + (y0+ty)*WW + (x0+tx2)) = __floats2half2_rn(ra, rb);
}

// ---------------------------------------------------------------------------
// K3: fc2 (fp16 mma.sync) + fused KV of xc via fp16 smem reduce (half2 loads).
// smem bytes: AH 0 (9216), XH 9216 (17408); v_s alias of XH: [128][66] f16 (16896);
//             KT 26624 (2048 f16), INV 28672 (256), BETA 28928 (256) -> 29184
// ---------------------------------------------------------------------------
#define C_AH  0
#define C_XH  9216
#define C_VS  9216     // alias of XH: [128][66] half
#define C_KT  26624
#define C_INV 28672
#define C_BETA 28928
#define C_SMEM 29184
#define VSS 66         // v_s row stride (halves)

__global__ __launch_bounds__(256,4) void k_fc2kv(
    const float* __restrict__ fc2_bn)
{
    extern __shared__ char sm[];
    __half* aH = (__half*)(sm + C_AH);
    __half* xH = (__half*)(sm + C_XH);
    __half* K_s = (__half*)(sm + C_KT);
    float* s_inv = (float*)(sm + C_INV);
    float* s_beta= (float*)(sm + C_BETA);
    __half* v_s  = (__half*)(sm + C_VS);   // alias, used after mainloop
    uint32_t sb = smem_u32(sm);

    int tid = threadIdx.x;
    int b  = blockIdx.y;
    int n0 = blockIdx.x * TPX;

    // weights: raw fp16 copy (pre-converted)
    for (int i=tid; i<64*8; i+=256){
        int o = i>>3, c8 = (i&7)<<3;
        *(uint4*)(aH + o*WS + c8) = *(const uint4*)(g_wC + o*64 + c8);
    }
    // s tile [64 ch][128 px] — raw fp16 copy
    const __half* sp = g_s + (size_t)b*CC*NN + n0;
    for (int i=tid; i<64*16; i+=256){
        int c = i>>4, p8 = (i&15)<<3;
        *(uint4*)(xH + c*XS + p8) = *(const uint4*)(sp + (size_t)c*NN + p8);
    }
    // K tile [8][128] fp16 raw copy
    {
        const __half* kp = g_K + (size_t)b*MM*NN + n0;
        int m = tid >> 5, p4 = (tid & 31)*4;
        *(uint2*)(K_s + m*TPX + p4) = *(const uint2*)(kp + (size_t)m*NN + p4);
    }
    if (tid < 64){
        float sc=fc2_bn[0*CC+tid], bi=fc2_bn[1*CC+tid];
        float mn=fc2_bn[2*CC+tid], vr=fc2_bn[3*CC+tid];
        float inv = sc*rsqrtf(vr+1e-5f);
        s_inv[tid]=inv; s_beta[tid]=bi-mn*inv;
    }
    __syncthreads();

    int w = tid >> 5, lane = tid & 31;
    int mt = w & 3, ph = w >> 2;
    int m0 = mt*16, p0 = ph*64;

    float acc[8][4];
    #pragma unroll
    for (int i=0;i<8;i++){ acc[i][0]=acc[i][1]=acc[i][2]=acc[i][3]=0.f; }

    int arow = m0 + (lane & 15), acol8 = (lane>>4)*8;
    int brow = (lane & 7) + 8*((lane>>3)&1), bcol8 = (lane>>4)*8;

    #pragma unroll
    for (int kt=0; kt<4; kt++){
        int k0 = kt*16;
        uint32_t a[4];
        ldsm4(a, sb + C_AH + (uint32_t)(arow*WS + k0 + acol8)*2);
        #pragma unroll
        for (int np=0; np<4; np++){
            uint32_t bF[4];
            ldsm4t(bF, sb + C_XH + (uint32_t)((k0+brow)*XS + p0 + np*16 + bcol8)*2);
            mma16816h(acc[2*np],   a, bF);
            mma16816h(acc[2*np+1], a, bF+2);
        }
    }

    __syncthreads();   // everyone done reading xH -> reuse as v_s (fp16)

    // epilogue: xc = relu6(bn(D)) -> fp16 smem
    int g = lane >> 2, t2 = (lane & 3)*2;
    int o0 = m0 + g, o1 = o0 + 8;
    float i0 = s_inv[o0], e0 = s_beta[o0], i1 = s_inv[o1], e1 = s_beta[o1];
    #pragma unroll
    for (int nt=0; nt<8; nt++){
        int px = p0 + nt*8 + t2;
        v_s[ px   *VSS + o0] = __float2half(relu6f(acc[nt][0]*i0+e0));
        v_s[(px+1)*VSS + o0] = __float2half(relu6f(acc[nt][1]*i0+e0));
        v_s[ px   *VSS + o1] = __float2half(relu6f(acc[nt][2]*i1+e1));
        v_s[(px+1)*VSS + o1] = __float2half(relu6f(acc[nt][3]*i1+e1));
    }
    __syncthreads();

    // KV reduction over xc: 8 m-groups x 32 channel-pairs, half2 loads + HFMA2
    {
        int m = tid >> 5, cp = (tid & 31)*2;   // channels cp, cp+1
        const __half* kr = K_s + m*TPX;
        half2 acc0 = __floats2half2_rn(0.f,0.f);
        half2 acc1 = __floats2half2_rn(0.f,0.f);
        #pragma unroll 8
        for (int p=0; p<TPX; p+=2){
            half2 kk = *(const half2*)(kr + p);
            half2 v0 = *(const half2*)(v_s +  p   *VSS + cp);
            half2 v1 = *(const half2*)(v_s + (p+1)*VSS + cp);
            acc0 = __hfma2(__half2half2(__low2half(kk)),  v0, acc0);
            acc1 = __hfma2(__half2half2(__high2half(kk)), v1, acc1);
        }
        float2 f0 = __half22float2(acc0);
        float2 f1 = __half22float2(acc1);
        float* kvb = g_KV + b*MM*CC + m*CC;
        atomicAdd(kvb + cp,     f0.x + f1.x);
        atomicAdd(kvb + cp + 1, f0.y + f1.y);
    }
}

// ---------------------------------------------------------------------------
// K5: out = x + gamma * (Qt . KV) * norm.
// 4 px/thread (float4), 4-way channel split (16 ch each); Q read fp16.
// ---------------------------------------------------------------------------
__global__ __launch_bounds__(256) void k_out(
    const float* __restrict__ x, const float* __restrict__ gamma,
    float* __restrict__ out)
{
    __shared__ __align__(16) float s_kv[MM*16];
    __shared__ float s_ks[MM];
    int tid = threadIdx.x;
    int p4 = (blockIdx.x*256 + tid)*4;
    int b = p4/NN, n = p4%NN;     // 1024 | NN -> b block-uniform
    int co = blockIdx.y*16;

    if (tid < MM*16){
        int m = tid>>4, j = tid&15;
        s_kv[tid] = g_KV[b*MM*CC + m*CC + co + j];
    }
    if (tid<MM) s_ks[tid] = g_Ksum[b*MM+tid] + 1e-6f;
    __syncthreads();

    float4 q[MM];
    #pragma unroll
    for (int m=0;m<MM;m++){
        uint2 qr = *(const uint2*)(g_Q + (size_t)b*MM*NN + (size_t)m*NN + n);
        float2 q01 = __half22float2(*(half2*)&qr.x);
        float2 q23 = __half22float2(*(half2*)&qr.y);
        q[m] = make_float4(q01.x, q01.y, q23.x, q23.y);
    }

    float4 den = make_float4(0.f,0.f,0.f,0.f);
    #pragma unroll
    for (int m=0;m<MM;m++){
        float ks = s_ks[m];
        den.x = fmaf(q[m].x, ks, den.x); den.y = fmaf(q[m].y, ks, den.y);
        den.z = fmaf(q[m].z, ks, den.z); den.w = fmaf(q[m].w, ks, den.w);
    }
    float gm = gamma[0];
    float4 gs = make_float4(gm/den.x, gm/den.y, gm/den.z, gm/den.w);

    const float* xb = x + (size_t)b*CC*NN + (size_t)co*NN + n;
    float* ob = out + (size_t)b*CC*NN + (size_t)co*NN + n;

    #pragma unroll 4
    for (int c=0;c<16;c++){
        float ax=0.f, ay=0.f, az=0.f, aw=0.f;
        #pragma unroll
        for (int m=0;m<MM;m++){
            float wv = s_kv[m*16 + c];
            ax = fmaf(q[m].x, wv, ax); ay = fmaf(q[m].y, wv, ay);
            az = fmaf(q[m].z, wv, az); aw = fmaf(q[m].w, wv, aw);
        }
        float4 xv = *(const float4*)(xb + (size_t)c*NN);
        xv.x = fmaf(gs.x, ax, xv.x); xv.y = fmaf(gs.y, ay, xv.y);
        xv.z = fmaf(gs.z, az, xv.z); xv.w = fmaf(gs.w, aw, xv.w);
        *(float4*)(ob + (size_t)c*NN) = xv;
    }
}

// ---------------------------------------------------------------------------
extern "C" void kernel_launch(void* const* d_in, const int* in_sizes, int n_in,
                              void* d_out, int out_size)
{
    const float* x      = (const float*)d_in[0];
    const float* gamma  = (const float*)d_in[1];
    const float* q_w    = (const float*)d_in[2];
    const float* q_b    = (const float*)d_in[3];
    const float* k_w    = (const float*)d_in[4];
    const float* k_b    = (const float*)d_in[5];
    const float* v_w    = (const float*)d_in[6];
    const float* v_b    = (const float*)d_in[7];
    const float* fc1_w  = (const float*)d_in[8];
    const float* fc1_bn = (const float*)d_in[9];
    const float* c1_w   = (const float*)d_in[10];
    const float* c1_bn  = (const float*)d_in[11];
    const float* c2_w   = (const float*)d_in[12];
    const float* c2_bn  = (const float*)d_in[13];
    const float* fc2_w  = (const float*)d_in[14];
    const float* fc2_bn = (const float*)d_in[15];
    float* out = (float*)d_out;

    cudaFuncSetAttribute(k_front,  cudaFuncAttributeMaxDynamicSharedMemorySize, F_SMEM);
    cudaFuncSetAttribute(k_fc2kv,  cudaFuncAttributeMaxDynamicSharedMemorySize, C_SMEM);

    k_prep<<<16,256>>>(q_w,k_w,v_w,fc1_w,fc2_w);
    k_front<<<dim3(NN/TPX,BB),288,F_SMEM>>>(x,q_b,k_b,v_b,fc1_bn);
    k_dw<<<dim3(WW/32,HH/16,BB*CC),dim3(16,16)>>>(c1_w,c1_bn,c2_w,c2_bn);
    k_fc2kv<<<dim3(NN/TPX,BB),256,C_SMEM>>>(fc2_bn);
    k_out<<<dim3(BN/1024,4),256>>>(x,gamma,out);
}